// round 1
// baseline (speedup 1.0000x reference)
#include <cuda_runtime.h>
#include <cstdint>
#include <cstddef>

// Problem constants
#define B_NW   8192
#define NTOK   64
#define CDIM   256
#define NH     8
#define HD     32
#define MROWS  (B_NW * NTOK)          // 524288
#define QKV_N  (3 * CDIM)             // 768
#define SCALE  0.17677669529663687f   // 32^-0.5

// ---------------------------------------------------------------------------
// Static device scratch (allocation-free contract: __device__ globals)
// ---------------------------------------------------------------------------
__device__ float g_qkv[(size_t)MROWS * QKV_N];   // 1.61 GB: [M, 768] = Q|K|V
__device__ float g_att[(size_t)MROWS * CDIM];    // 512 MB:  attention output [M, 256]

// ---------------------------------------------------------------------------
// f32x2 packed-FMA helpers (PTX-only path; doubles fp32 FMA throughput)
// ---------------------------------------------------------------------------
__device__ __forceinline__ unsigned long long pack2(float a) {
    unsigned long long r;
    asm("mov.b64 %0, {%1, %1};" : "=l"(r) : "f"(a));
    return r;
}
__device__ __forceinline__ void ffma2(unsigned long long& acc,
                                      unsigned long long a,
                                      unsigned long long b) {
    asm("fma.rn.f32x2 %0, %1, %2, %0;" : "+l"(acc) : "l"(a), "l"(b));
}
__device__ __forceinline__ float2 unpack2(unsigned long long v) {
    float2 r;
    asm("mov.b64 {%0, %1}, %2;" : "=f"(r.x), "=f"(r.y) : "l"(v));
    return r;
}

// ---------------------------------------------------------------------------
// GEMM (NT): C[M,Ncols] = A[M,256] @ W[Ncols,256]^T + bias
// Block tile 128x128, 256 threads, 8x8 micro-tile, K-chunk 8.
// Requires M % 128 == 0, Ncols % 128 == 0 (524288 % 128 == 0, 768/256 ok).
// ---------------------------------------------------------------------------
__global__ __launch_bounds__(256)
void gemm_nt_kernel(const float* __restrict__ A,
                    const float* __restrict__ W,
                    const float* __restrict__ bias,
                    float* __restrict__ C,
                    int Ncols)
{
    __shared__ float As[8][132];   // [k][row], padded; 132*4B = 33*16B keeps f4 align
    __shared__ float Bs[8][132];   // [k][col]

    const int t    = threadIdx.x;
    const int row0 = blockIdx.y * 128;
    const int col0 = blockIdx.x * 128;
    const int tx   = t & 15;       // col group
    const int ty   = t >> 4;       // row group

    const int lrow = t >> 1;       // 0..127 (load row)
    const int lk4  = (t & 1) * 4;  // 0 or 4 (load k-offset)

    unsigned long long acc[8][4];
#pragma unroll
    for (int i = 0; i < 8; i++)
#pragma unroll
        for (int j = 0; j < 4; j++) acc[i][j] = 0ULL;

    const float* Aptr = A + (size_t)(row0 + lrow) * CDIM + lk4;
    const float* Wptr = W + (size_t)(col0 + lrow) * CDIM + lk4;

    for (int kc = 0; kc < CDIM; kc += 8) {
        float4 av = *(const float4*)(Aptr + kc);
        float4 wv = *(const float4*)(Wptr + kc);

        __syncthreads();   // previous chunk's compute done before overwrite
        As[lk4 + 0][lrow] = av.x;  As[lk4 + 1][lrow] = av.y;
        As[lk4 + 2][lrow] = av.z;  As[lk4 + 3][lrow] = av.w;
        Bs[lk4 + 0][lrow] = wv.x;  Bs[lk4 + 1][lrow] = wv.y;
        Bs[lk4 + 2][lrow] = wv.z;  Bs[lk4 + 3][lrow] = wv.w;
        __syncthreads();

#pragma unroll
        for (int k = 0; k < 8; k++) {
            float4 a0 = *(const float4*)&As[k][ty * 8];
            float4 a1 = *(const float4*)&As[k][ty * 8 + 4];
            ulonglong2 bb0 = *(const ulonglong2*)&Bs[k][tx * 8];
            ulonglong2 bb1 = *(const ulonglong2*)&Bs[k][tx * 8 + 4];
            unsigned long long bp[4] = { bb0.x, bb0.y, bb1.x, bb1.y };
            float af[8] = { a0.x, a0.y, a0.z, a0.w, a1.x, a1.y, a1.z, a1.w };
#pragma unroll
            for (int i = 0; i < 8; i++) {
                unsigned long long ap = pack2(af[i]);
#pragma unroll
                for (int j = 0; j < 4; j++) ffma2(acc[i][j], ap, bp[j]);
            }
        }
    }

    // epilogue
    float4 bv0 = *(const float4*)&bias[col0 + tx * 8];
    float4 bv1 = *(const float4*)&bias[col0 + tx * 8 + 4];
#pragma unroll
    for (int i = 0; i < 8; i++) {
        int row = row0 + ty * 8 + i;
        float2 p0 = unpack2(acc[i][0]);
        float2 p1 = unpack2(acc[i][1]);
        float2 p2 = unpack2(acc[i][2]);
        float2 p3 = unpack2(acc[i][3]);
        float4 r0 = { p0.x + bv0.x, p0.y + bv0.y, p1.x + bv0.z, p1.y + bv0.w };
        float4 r1 = { p2.x + bv1.x, p2.y + bv1.y, p3.x + bv1.z, p3.y + bv1.w };
        float* cp = C + (size_t)row * Ncols + col0 + tx * 8;
        *(float4*)cp       = r0;
        *(float4*)(cp + 4) = r1;
    }
}

// ---------------------------------------------------------------------------
// Window attention: one block per (window b, head h). 256 threads.
// qkv: [M, 768] with col = which*256 + h*32 + d  (which: 0=Q,1=K,2=V)
// out: [M, 256] with col = h*32 + d
// ---------------------------------------------------------------------------
__global__ __launch_bounds__(256)
void attn_kernel(const float* __restrict__ qkv,
                 const float* __restrict__ table,  // [225, 8]
                 const int*   __restrict__ rpi,    // [64, 64]
                 float* __restrict__ out)
{
    __shared__ float qs[NTOK][36];   // stride 36 avoids bank conflicts, keeps f4 align
    __shared__ float ks[NTOK][36];
    __shared__ float vs[NTOK][36];
    __shared__ float sc[NTOK][68];   // scores, stride 68

    const int b = blockIdx.x;
    const int h = blockIdx.y;
    const int t = threadIdx.x;

    const float* base = qkv + (size_t)b * NTOK * QKV_N;

    // Load q, k, v tiles: 3 * 64 rows * 8 float4 = 1536 float4 loads
    for (int i = t; i < 3 * 512; i += 256) {
        int which = i >> 9;          // 0,1,2
        int rem   = i & 511;
        int r     = rem >> 3;
        int f     = rem & 7;
        float4 v4 = *(const float4*)(base + (size_t)r * QKV_N + which * CDIM + h * HD + f * 4);
        float* dst = (which == 0) ? &qs[r][f * 4] : (which == 1) ? &ks[r][f * 4] : &vs[r][f * 4];
        *(float4*)dst = v4;
    }
    __syncthreads();

    // Scores: thread handles row r = t>>2, key quarter m0 = (t&3)*16
    {
        const int r  = t >> 2;
        const int m0 = (t & 3) * 16;
        float qreg[HD];
#pragma unroll
        for (int d = 0; d < HD; d++) qreg[d] = qs[r][d];
#pragma unroll 4
        for (int mi = 0; mi < 16; mi++) {
            int m = m0 + mi;
            float s = 0.f;
#pragma unroll
            for (int d = 0; d < HD; d++) s += qreg[d] * ks[m][d];
            int idx = __ldg(&rpi[r * NTOK + m]);
            s = s * SCALE + __ldg(&table[idx * NH + h]);
            sc[r][m] = s;
        }
    }
    __syncthreads();

    // Softmax per row (threads 0..63)
    if (t < NTOK) {
        const int r = t;
        float mx = -1e30f;
#pragma unroll 8
        for (int m = 0; m < NTOK; m++) mx = fmaxf(mx, sc[r][m]);
        float sum = 0.f;
        float e[NTOK];
#pragma unroll 8
        for (int m = 0; m < NTOK; m++) { e[m] = __expf(sc[r][m] - mx); sum += e[m]; }
        float inv = 1.f / sum;
#pragma unroll 8
        for (int m = 0; m < NTOK; m++) sc[r][m] = e[m] * inv;
    }
    __syncthreads();

    // Out: thread handles row r = t>>2, d-slice d0 = (t&3)*8
    {
        const int r  = t >> 2;
        const int d0 = (t & 3) * 8;
        float4 o0 = { 0.f, 0.f, 0.f, 0.f };
        float4 o1 = { 0.f, 0.f, 0.f, 0.f };
#pragma unroll 8
        for (int m = 0; m < NTOK; m++) {
            float p = sc[r][m];
            float4 v0 = *(const float4*)&vs[m][d0];
            float4 v1 = *(const float4*)&vs[m][d0 + 4];
            o0.x += p * v0.x; o0.y += p * v0.y; o0.z += p * v0.z; o0.w += p * v0.w;
            o1.x += p * v1.x; o1.y += p * v1.y; o1.z += p * v1.z; o1.w += p * v1.w;
        }
        float* op = out + (size_t)(b * NTOK + r) * CDIM + h * HD + d0;
        *(float4*)op       = o0;
        *(float4*)(op + 4) = o1;
    }
}

// ---------------------------------------------------------------------------
// Launch
// ---------------------------------------------------------------------------
extern "C" void kernel_launch(void* const* d_in, const int* in_sizes, int n_in,
                              void* d_out, int out_size)
{
    const float* x       = (const float*)d_in[0];  // [8192, 64, 256]
    const float* qkv_w   = (const float*)d_in[1];  // [768, 256]
    const float* qkv_b   = (const float*)d_in[2];  // [768]
    const float* proj_w  = (const float*)d_in[3];  // [256, 256]
    const float* proj_b  = (const float*)d_in[4];  // [256]
    const float* table   = (const float*)d_in[5];  // [225, 8]
    const int*   rpi     = (const int*)  d_in[6];  // [64, 64]
    float*       out     = (float*)d_out;          // [8192, 64, 256]

    float* qkv_scratch = nullptr;
    float* att_scratch = nullptr;
    cudaGetSymbolAddress((void**)&qkv_scratch, g_qkv);
    cudaGetSymbolAddress((void**)&att_scratch, g_att);

    // 1) QKV projection: [524288, 768]
    gemm_nt_kernel<<<dim3(QKV_N / 128, MROWS / 128), 256>>>(
        x, qkv_w, qkv_b, qkv_scratch, QKV_N);

    // 2) Window attention per (window, head)
    attn_kernel<<<dim3(B_NW, NH), 256>>>(qkv_scratch, table, rpi, att_scratch);

    // 3) Output projection: [524288, 256]
    gemm_nt_kernel<<<dim3(CDIM / 128, MROWS / 128), 256>>>(
        att_scratch, proj_w, proj_b, out, CDIM);
}

// round 4
// speedup vs baseline: 1.5013x; 1.5013x over previous
#include <cuda_runtime.h>
#include <cstdint>
#include <cstddef>

// ---------------------------------------------------------------------------
// Problem constants
// ---------------------------------------------------------------------------
#define B_NW   8192
#define NTOK   64
#define CDIM   256
#define NH     8
#define HD     32
#define MROWS  (B_NW * NTOK)          // 524288
#define QKV_N  768
#define SCALE  0.17677669529663687f   // 32^-0.5

// GEMM tiling (mma.sync m16n8k8 tf32)
#define BM   128
#define BN   128
#define BK   32
#define NCHUNK (CDIM / BK)            // 8
#define PITCH (BK + 4)                // 36 floats: conflict-free frag loads
#define ASZ  (BM * PITCH)             // floats
#define BSZ  (BN * PITCH)
#define SMEM_DYN (2 * (ASZ + BSZ) * 4)  // 73728 B

// ---------------------------------------------------------------------------
// Static device scratch
// ---------------------------------------------------------------------------
__device__ float g_qkv[(size_t)MROWS * QKV_N];   // QKV output [M, 768]
__device__ float g_att[(size_t)MROWS * CDIM];    // attention output [M, 256]

// ---------------------------------------------------------------------------
// Helpers
// ---------------------------------------------------------------------------
__device__ __forceinline__ uint32_t s2u(const void* p) {
    uint32_t a;
    asm("{ .reg .u64 t; cvta.to.shared.u64 t, %1; cvt.u32.u64 %0, t; }"
        : "=r"(a) : "l"(p));
    return a;
}

__device__ __forceinline__ uint32_t ctf(float x) {   // fp32 -> tf32 (RN), as b32
    uint32_t u;
    asm("cvt.rna.tf32.f32 %0, %1;" : "=r"(u) : "f"(x));
    return u;
}

__device__ __forceinline__ void cp16(uint32_t dst, const void* src) {
    asm volatile("cp.async.cg.shared.global [%0], [%1], 16;"
                 :: "r"(dst), "l"(src) : "memory");
}

__device__ __forceinline__ void mma8(float* c, const uint32_t* a, const uint32_t* b) {
    asm volatile(
        "mma.sync.aligned.m16n8k8.row.col.f32.tf32.tf32.f32 "
        "{%0,%1,%2,%3}, {%4,%5,%6,%7}, {%8,%9}, {%0,%1,%2,%3};"
        : "+f"(c[0]), "+f"(c[1]), "+f"(c[2]), "+f"(c[3])
        : "r"(a[0]), "r"(a[1]), "r"(a[2]), "r"(a[3]), "r"(b[0]), "r"(b[1]));
}

// ---------------------------------------------------------------------------
// tf32 mma.sync GEMM (NT): C[M,Ncols] = A[M,256] @ W[Ncols,256]^T + bias
// CTA 128x128, 256 threads (8 warps as 2x4 -> 64x32 warp tiles),
// BK=32 double-buffered cp.async. Inputs rounded to tf32 in-register.
// ---------------------------------------------------------------------------
__global__ __launch_bounds__(256)
void gemm_mma_kernel(const float* __restrict__ A,
                     const float* __restrict__ W,
                     const float* __restrict__ bias,
                     float* __restrict__ C,
                     int Ncols)
{
    extern __shared__ float sm[];
    float* As[2] = { sm,             sm + ASZ + BSZ };
    float* Bs[2] = { sm + ASZ,       sm + 2 * ASZ + BSZ };

    const int t      = threadIdx.x;
    const int w      = t >> 5;
    const int lane   = t & 31;
    const int g      = lane >> 2;     // group id (0..7)
    const int tg     = lane & 3;      // thread in group
    const int warp_m = w >> 2;        // 0..1
    const int warp_n = w & 3;         // 0..3
    const size_t row0 = (size_t)blockIdx.y * BM;
    const int    col0 = blockIdx.x * BN;

    // per-chunk async loader: A 128x8 f4, B 128x8 f4; 8 f4 per thread
    auto load_chunk = [&](int kc, int buf) {
        const uint32_t aB = s2u(As[buf]);
        const uint32_t bB = s2u(Bs[buf]);
#pragma unroll
        for (int i = 0; i < 4; i++) {
            int u = t + 256 * i;
            int r = u >> 3, q = u & 7;
            cp16(aB + (uint32_t)(r * PITCH + q * 4) * 4,
                 A + (row0 + r) * CDIM + kc * BK + q * 4);
        }
#pragma unroll
        for (int i = 0; i < 4; i++) {
            int u = t + 256 * i;
            int r = u >> 3, q = u & 7;
            cp16(bB + (uint32_t)(r * PITCH + q * 4) * 4,
                 W + (size_t)(col0 + r) * CDIM + kc * BK + q * 4);
        }
        asm volatile("cp.async.commit_group;" ::: "memory");
    };

    float acc[4][4][4];
#pragma unroll
    for (int mi = 0; mi < 4; mi++)
#pragma unroll
        for (int ni = 0; ni < 4; ni++)
#pragma unroll
            for (int j = 0; j < 4; j++) acc[mi][ni][j] = 0.f;

    load_chunk(0, 0);

#pragma unroll
    for (int c = 0; c < NCHUNK; c++) {
        if (c + 1 < NCHUNK) {
            load_chunk(c + 1, (c + 1) & 1);
            asm volatile("cp.async.wait_group 1;" ::: "memory");
        } else {
            asm volatile("cp.async.wait_group 0;" ::: "memory");
        }
        __syncthreads();

        const float* aw = As[c & 1] + (warp_m * 64) * PITCH;
        const float* bw = Bs[c & 1] + (warp_n * 32) * PITCH;

#pragma unroll
        for (int ks = 0; ks < 4; ks++) {
            const int k0 = ks * 8;
            uint32_t af[4][4], bf[4][2];
#pragma unroll
            for (int mi = 0; mi < 4; mi++) {
                const float* p = aw + (mi * 16 + g) * PITCH + k0 + tg;
                af[mi][0] = ctf(p[0]);
                af[mi][1] = ctf(p[8 * PITCH]);
                af[mi][2] = ctf(p[4]);
                af[mi][3] = ctf(p[8 * PITCH + 4]);
            }
#pragma unroll
            for (int ni = 0; ni < 4; ni++) {
                const float* p = bw + (ni * 8 + g) * PITCH + k0 + tg;
                bf[ni][0] = ctf(p[0]);
                bf[ni][1] = ctf(p[4]);
            }
#pragma unroll
            for (int mi = 0; mi < 4; mi++)
#pragma unroll
                for (int ni = 0; ni < 4; ni++)
                    mma8(acc[mi][ni], af[mi], bf[ni]);
        }
        __syncthreads();
    }

    // epilogue: bias + store (float2 per fragment row)
#pragma unroll
    for (int ni = 0; ni < 4; ni++) {
        const int col = col0 + warp_n * 32 + ni * 8 + 2 * tg;
        const float bx = __ldg(&bias[col]);
        const float by = __ldg(&bias[col + 1]);
#pragma unroll
        for (int mi = 0; mi < 4; mi++) {
            const size_t rlo = row0 + warp_m * 64 + mi * 16 + g;
            float2 v0 = { acc[mi][ni][0] + bx, acc[mi][ni][1] + by };
            float2 v1 = { acc[mi][ni][2] + bx, acc[mi][ni][3] + by };
            *(float2*)(C + rlo * (size_t)Ncols + col)       = v0;
            *(float2*)(C + (rlo + 8) * (size_t)Ncols + col) = v1;
        }
    }
}

// ---------------------------------------------------------------------------
// Window attention: one block per (window b, head h). 256 threads. fp32.
// ---------------------------------------------------------------------------
__global__ __launch_bounds__(256)
void attn_kernel(const float* __restrict__ qkv,
                 const float* __restrict__ table,
                 const int*   __restrict__ rpi,
                 float* __restrict__ out)
{
    __shared__ float qs[NTOK][36];
    __shared__ float ks[NTOK][36];
    __shared__ float vs[NTOK][36];
    __shared__ float sc[NTOK][68];

    const int b = blockIdx.x;
    const int h = blockIdx.y;
    const int t = threadIdx.x;

    const float* base = qkv + (size_t)b * NTOK * QKV_N;

    for (int i = t; i < 3 * 512; i += 256) {
        int which = i >> 9;
        int rem   = i & 511;
        int r     = rem >> 3;
        int f     = rem & 7;
        float4 v4 = *(const float4*)(base + (size_t)r * QKV_N + which * CDIM + h * HD + f * 4);
        float* dst = (which == 0) ? &qs[r][f * 4] : (which == 1) ? &ks[r][f * 4] : &vs[r][f * 4];
        *(float4*)dst = v4;
    }
    __syncthreads();

    {
        const int r  = t >> 2;
        const int m0 = (t & 3) * 16;
        float qreg[HD];
#pragma unroll
        for (int d = 0; d < HD; d++) qreg[d] = qs[r][d];
#pragma unroll 4
        for (int mi = 0; mi < 16; mi++) {
            int m = m0 + mi;
            float s = 0.f;
#pragma unroll
            for (int d = 0; d < HD; d++) s += qreg[d] * ks[m][d];
            int idx = __ldg(&rpi[r * NTOK + m]);
            s = s * SCALE + __ldg(&table[idx * NH + h]);
            sc[r][m] = s;
        }
    }
    __syncthreads();

    if (t < NTOK) {
        const int r = t;
        float mx = -1e30f;
#pragma unroll 8
        for (int m = 0; m < NTOK; m++) mx = fmaxf(mx, sc[r][m]);
        float sum = 0.f;
        float e[NTOK];
#pragma unroll 8
        for (int m = 0; m < NTOK; m++) { e[m] = __expf(sc[r][m] - mx); sum += e[m]; }
        float inv = 1.f / sum;
#pragma unroll 8
        for (int m = 0; m < NTOK; m++) sc[r][m] = e[m] * inv;
    }
    __syncthreads();

    {
        const int r  = t >> 2;
        const int d0 = (t & 3) * 8;
        float4 o0 = { 0.f, 0.f, 0.f, 0.f };
        float4 o1 = { 0.f, 0.f, 0.f, 0.f };
#pragma unroll 8
        for (int m = 0; m < NTOK; m++) {
            float p = sc[r][m];
            float4 v0 = *(const float4*)&vs[m][d0];
            float4 v1 = *(const float4*)&vs[m][d0 + 4];
            o0.x += p * v0.x; o0.y += p * v0.y; o0.z += p * v0.z; o0.w += p * v0.w;
            o1.x += p * v1.x; o1.y += p * v1.y; o1.z += p * v1.z; o1.w += p * v1.w;
        }
        float* op = out + (size_t)(b * NTOK + r) * CDIM + h * HD + d0;
        *(float4*)op       = o0;
        *(float4*)(op + 4) = o1;
    }
}

// ---------------------------------------------------------------------------
// Launch
// ---------------------------------------------------------------------------
extern "C" void kernel_launch(void* const* d_in, const int* in_sizes, int n_in,
                              void* d_out, int out_size)
{
    const float* x       = (const float*)d_in[0];
    const float* qkv_w   = (const float*)d_in[1];
    const float* qkv_b   = (const float*)d_in[2];
    const float* proj_w  = (const float*)d_in[3];
    const float* proj_b  = (const float*)d_in[4];
    const float* table   = (const float*)d_in[5];
    const int*   rpi     = (const int*)  d_in[6];
    float*       out     = (float*)d_out;

    float *qkv_s, *att_s;
    cudaGetSymbolAddress((void**)&qkv_s, g_qkv);
    cudaGetSymbolAddress((void**)&att_s, g_att);

    cudaFuncSetAttribute(gemm_mma_kernel,
                         cudaFuncAttributeMaxDynamicSharedMemorySize, SMEM_DYN);

    // 1) QKV projection [524288, 768] (tf32 tensor cores)
    gemm_mma_kernel<<<dim3(QKV_N / BN, MROWS / BM), 256, SMEM_DYN>>>(
        x, qkv_w, qkv_b, qkv_s, QKV_N);

    // 2) Window attention (fp32)
    attn_kernel<<<dim3(B_NW, NH), 256>>>(qkv_s, table, rpi, att_s);

    // 3) Output projection [524288, 256] (tf32 tensor cores)
    gemm_mma_kernel<<<dim3(CDIM / BN, MROWS / BM), 256, SMEM_DYN>>>(
        att_s, proj_w, proj_b, out, CDIM);
}

// round 5
// speedup vs baseline: 3.4904x; 2.3249x over previous
#include <cuda_runtime.h>
#include <cstdint>
#include <cstddef>

// ---------------------------------------------------------------------------
// Problem constants
// ---------------------------------------------------------------------------
#define B_NW   8192
#define NTOK   64
#define CDIM   256
#define NH     8
#define HD     32
#define MROWS  (B_NW * NTOK)          // 524288
#define QKV_N  768
#define SCALE  0.17677669529663687f   // 32^-0.5

// GEMM tiling (mma.sync m16n8k8 tf32)
#define BM   128
#define BN   128
#define BK   32
#define NCHUNK (CDIM / BK)            // 8
#define PITCH (BK + 4)                // 36 floats
#define ASZ  (BM * PITCH)
#define BSZ  (BN * PITCH)
#define SMEM_DYN (2 * (ASZ + BSZ) * 4)  // 73728 B

// ---------------------------------------------------------------------------
// Static device scratch
// ---------------------------------------------------------------------------
__device__ float g_qkv[(size_t)MROWS * QKV_N];   // QKV output [M, 768]
__device__ float g_att[(size_t)MROWS * CDIM];    // attention output [M, 256]
__device__ float g_bias[NH * NTOK * NTOK];       // precomputed rel-pos bias

// ---------------------------------------------------------------------------
// Helpers
// ---------------------------------------------------------------------------
__device__ __forceinline__ uint32_t s2u(const void* p) {
    uint32_t a;
    asm("{ .reg .u64 t; cvta.to.shared.u64 t, %1; cvt.u32.u64 %0, t; }"
        : "=r"(a) : "l"(p));
    return a;
}

__device__ __forceinline__ uint32_t ctf(float x) {   // fp32 -> tf32 (RN)
    uint32_t u;
    asm("cvt.rna.tf32.f32 %0, %1;" : "=r"(u) : "f"(x));
    return u;
}

__device__ __forceinline__ void cp16(uint32_t dst, const void* src) {
    asm volatile("cp.async.cg.shared.global [%0], [%1], 16;"
                 :: "r"(dst), "l"(src) : "memory");
}

__device__ __forceinline__ void mma8(float* c, const uint32_t* a, const uint32_t* b) {
    asm volatile(
        "mma.sync.aligned.m16n8k8.row.col.f32.tf32.tf32.f32 "
        "{%0,%1,%2,%3}, {%4,%5,%6,%7}, {%8,%9}, {%0,%1,%2,%3};"
        : "+f"(c[0]), "+f"(c[1]), "+f"(c[2]), "+f"(c[3])
        : "r"(a[0]), "r"(a[1]), "r"(a[2]), "r"(a[3]), "r"(b[0]), "r"(b[1]));
}

// Fast exp on the FMA pipe (no MUFU). Deg-5 Taylor of 2^f, f in [-0.5, 0.5].
// Relative error ~2.4e-6. Valid for x <= 0 (post max-subtraction).
__device__ __forceinline__ float fexp(float x) {
    float t = fmaxf(x * 1.4426950408889634f, -126.0f);
    float j = rintf(t);
    float f = t - j;
    float p =               1.33335581e-3f;
    p = __fmaf_rn(p, f, 9.61812911e-3f);
    p = __fmaf_rn(p, f, 5.55041087e-2f);
    p = __fmaf_rn(p, f, 2.40226507e-1f);
    p = __fmaf_rn(p, f, 6.93147181e-1f);
    p = __fmaf_rn(p, f, 1.0f);
    int ji = (int)j;
    return p * __int_as_float((ji + 127) << 23);
}

// ---------------------------------------------------------------------------
// Precompute bias matrix per head: g_bias[h][r][m] = table[rpi[r*64+m]*8 + h]
// ---------------------------------------------------------------------------
__global__ __launch_bounds__(256)
void bias_kernel(const float* __restrict__ table, const int* __restrict__ rpi,
                 float* __restrict__ gb) {
    int h = blockIdx.y;
    int i = blockIdx.x * 256 + threadIdx.x;     // 0..4095
    gb[h * 4096 + i] = table[rpi[i] * NH + h];
}

// ---------------------------------------------------------------------------
// tf32 mma.sync GEMM (NT): C[M,Ncols] = A[M,256] @ W[Ncols,256]^T + bias
// ---------------------------------------------------------------------------
__global__ __launch_bounds__(256, 2)
void gemm_mma_kernel(const float* __restrict__ A,
                     const float* __restrict__ W,
                     const float* __restrict__ bias,
                     float* __restrict__ C,
                     int Ncols)
{
    extern __shared__ float sm[];
    float* As[2] = { sm,       sm + ASZ + BSZ };
    float* Bs[2] = { sm + ASZ, sm + 2 * ASZ + BSZ };

    const int t      = threadIdx.x;
    const int w      = t >> 5;
    const int lane   = t & 31;
    const int g      = lane >> 2;
    const int tg     = lane & 3;
    const int warp_m = w >> 2;
    const int warp_n = w & 3;
    const size_t row0 = (size_t)blockIdx.y * BM;
    const int    col0 = blockIdx.x * BN;

    auto load_chunk = [&](int kc, int buf) {
        const uint32_t aB = s2u(As[buf]);
        const uint32_t bB = s2u(Bs[buf]);
#pragma unroll
        for (int i = 0; i < 4; i++) {
            int u = t + 256 * i;
            int r = u >> 3, q = u & 7;
            cp16(aB + (uint32_t)(r * PITCH + q * 4) * 4,
                 A + (row0 + r) * CDIM + kc * BK + q * 4);
        }
#pragma unroll
        for (int i = 0; i < 4; i++) {
            int u = t + 256 * i;
            int r = u >> 3, q = u & 7;
            cp16(bB + (uint32_t)(r * PITCH + q * 4) * 4,
                 W + (size_t)(col0 + r) * CDIM + kc * BK + q * 4);
        }
        asm volatile("cp.async.commit_group;" ::: "memory");
    };

    float acc[4][4][4];
#pragma unroll
    for (int mi = 0; mi < 4; mi++)
#pragma unroll
        for (int ni = 0; ni < 4; ni++)
#pragma unroll
            for (int j = 0; j < 4; j++) acc[mi][ni][j] = 0.f;

    load_chunk(0, 0);

#pragma unroll
    for (int c = 0; c < NCHUNK; c++) {
        if (c + 1 < NCHUNK) {
            load_chunk(c + 1, (c + 1) & 1);
            asm volatile("cp.async.wait_group 1;" ::: "memory");
        } else {
            asm volatile("cp.async.wait_group 0;" ::: "memory");
        }
        __syncthreads();

        const float* aw = As[c & 1] + (warp_m * 64) * PITCH;
        const float* bw = Bs[c & 1] + (warp_n * 32) * PITCH;

#pragma unroll
        for (int ks = 0; ks < 4; ks++) {
            const int k0 = ks * 8;
            uint32_t af[4][4], bf[4][2];
#pragma unroll
            for (int mi = 0; mi < 4; mi++) {
                const float* p = aw + (mi * 16 + g) * PITCH + k0 + tg;
                af[mi][0] = ctf(p[0]);
                af[mi][1] = ctf(p[8 * PITCH]);
                af[mi][2] = ctf(p[4]);
                af[mi][3] = ctf(p[8 * PITCH + 4]);
            }
#pragma unroll
            for (int ni = 0; ni < 4; ni++) {
                const float* p = bw + (ni * 8 + g) * PITCH + k0 + tg;
                bf[ni][0] = ctf(p[0]);
                bf[ni][1] = ctf(p[4]);
            }
#pragma unroll
            for (int mi = 0; mi < 4; mi++)
#pragma unroll
                for (int ni = 0; ni < 4; ni++)
                    mma8(acc[mi][ni], af[mi], bf[ni]);
        }
        __syncthreads();
    }

#pragma unroll
    for (int ni = 0; ni < 4; ni++) {
        const int col = col0 + warp_n * 32 + ni * 8 + 2 * tg;
        const float bx = __ldg(&bias[col]);
        const float by = __ldg(&bias[col + 1]);
#pragma unroll
        for (int mi = 0; mi < 4; mi++) {
            const size_t rlo = row0 + warp_m * 64 + mi * 16 + g;
            float2 v0 = { acc[mi][ni][0] + bx, acc[mi][ni][1] + by };
            float2 v1 = { acc[mi][ni][2] + bx, acc[mi][ni][3] + by };
            *(float2*)(C + rlo * (size_t)Ncols + col)       = v0;
            *(float2*)(C + (rlo + 8) * (size_t)Ncols + col) = v1;
        }
    }
}

// ---------------------------------------------------------------------------
// Window attention: one block per (window b, head h). 256 threads.
//   score:  16x16 thread grid, 4x4 register tiles, transposed-K smem tile
//   softmax: 4 threads/row, shuffle reductions, FMA-pipe exp
//   out:    2 rows x 4 cols per thread
// ---------------------------------------------------------------------------
__global__ __launch_bounds__(256)
void attn_kernel(const float* __restrict__ qkv,
                 const float* __restrict__ gbias,
                 float* __restrict__ out)
{
    __shared__ float qs[NTOK][36];    // q (pre-scaled by SCALE)
    __shared__ float kT[HD][68];      // transposed k: [d][m]
    __shared__ float vs[NTOK][36];
    __shared__ float sc[NTOK][68];    // scores -> exp values
    __shared__ float s_inv[NTOK];     // 1/rowsum

    const int b = blockIdx.x;
    const int h = blockIdx.y;
    const int t = threadIdx.x;

    const float* base  = qkv + (size_t)b * NTOK * QKV_N;
    const float* biash = gbias + h * NTOK * NTOK;

    // ---- load q (scaled), kT (transposed), v ----
    for (int i = t; i < 3 * 512; i += 256) {
        int which = i >> 9;
        int rem   = i & 511;
        int r     = rem >> 3;
        int f     = rem & 7;
        float4 v4 = *(const float4*)(base + (size_t)r * QKV_N + which * CDIM + h * HD + f * 4);
        if (which == 0) {
            v4.x *= SCALE; v4.y *= SCALE; v4.z *= SCALE; v4.w *= SCALE;
            *(float4*)&qs[r][f * 4] = v4;
        } else if (which == 1) {
            kT[f * 4 + 0][r] = v4.x;
            kT[f * 4 + 1][r] = v4.y;
            kT[f * 4 + 2][r] = v4.z;
            kT[f * 4 + 3][r] = v4.w;
        } else {
            *(float4*)&vs[r][f * 4] = v4;
        }
    }
    __syncthreads();

    // ---- scores: thread (ti, tj) computes rows 4ti..+3 x cols 4tj..+3 ----
    {
        const int ti = t >> 4;
        const int tj = t & 15;
        const int r0 = ti * 4;
        const int m0 = tj * 4;
        float acc[4][4];
#pragma unroll
        for (int i = 0; i < 4; i++)
#pragma unroll
            for (int j = 0; j < 4; j++) acc[i][j] = 0.f;

#pragma unroll
        for (int dc = 0; dc < 8; dc++) {
            float4 qv[4], kv[4];
#pragma unroll
            for (int i = 0; i < 4; i++) qv[i] = *(const float4*)&qs[r0 + i][dc * 4];
#pragma unroll
            for (int s = 0; s < 4; s++) kv[s] = *(const float4*)&kT[dc * 4 + s][m0];
#pragma unroll
            for (int i = 0; i < 4; i++) {
                acc[i][0] += qv[i].x * kv[0].x + qv[i].y * kv[1].x
                           + qv[i].z * kv[2].x + qv[i].w * kv[3].x;
                acc[i][1] += qv[i].x * kv[0].y + qv[i].y * kv[1].y
                           + qv[i].z * kv[2].y + qv[i].w * kv[3].y;
                acc[i][2] += qv[i].x * kv[0].z + qv[i].y * kv[1].z
                           + qv[i].z * kv[2].z + qv[i].w * kv[3].z;
                acc[i][3] += qv[i].x * kv[0].w + qv[i].y * kv[1].w
                           + qv[i].z * kv[2].w + qv[i].w * kv[3].w;
            }
        }
#pragma unroll
        for (int i = 0; i < 4; i++) {
            float4 bv = *(const float4*)(biash + (r0 + i) * NTOK + m0);
            float4 o = { acc[i][0] + bv.x, acc[i][1] + bv.y,
                         acc[i][2] + bv.z, acc[i][3] + bv.w };
            *(float4*)&sc[r0 + i][m0] = o;
        }
    }
    __syncthreads();

    // ---- softmax: 4 threads per row, 16 cols each ----
    {
        const int r   = t >> 2;
        const int seg = (t & 3) * 16;
        float4 v0 = *(const float4*)&sc[r][seg];
        float4 v1 = *(const float4*)&sc[r][seg + 4];
        float4 v2 = *(const float4*)&sc[r][seg + 8];
        float4 v3 = *(const float4*)&sc[r][seg + 12];
        float mx = fmaxf(fmaxf(fmaxf(v0.x, v0.y), fmaxf(v0.z, v0.w)),
                   fmaxf(fmaxf(fmaxf(v1.x, v1.y), fmaxf(v1.z, v1.w)),
                   fmaxf(fmaxf(fmaxf(v2.x, v2.y), fmaxf(v2.z, v2.w)),
                         fmaxf(fmaxf(v3.x, v3.y), fmaxf(v3.z, v3.w)))));
        mx = fmaxf(mx, __shfl_xor_sync(0xffffffffu, mx, 1, 4));
        mx = fmaxf(mx, __shfl_xor_sync(0xffffffffu, mx, 2, 4));

        v0.x = fexp(v0.x - mx); v0.y = fexp(v0.y - mx);
        v0.z = fexp(v0.z - mx); v0.w = fexp(v0.w - mx);
        v1.x = fexp(v1.x - mx); v1.y = fexp(v1.y - mx);
        v1.z = fexp(v1.z - mx); v1.w = fexp(v1.w - mx);
        v2.x = fexp(v2.x - mx); v2.y = fexp(v2.y - mx);
        v2.z = fexp(v2.z - mx); v2.w = fexp(v2.w - mx);
        v3.x = fexp(v3.x - mx); v3.y = fexp(v3.y - mx);
        v3.z = fexp(v3.z - mx); v3.w = fexp(v3.w - mx);

        float sum = (v0.x + v0.y + v0.z + v0.w) + (v1.x + v1.y + v1.z + v1.w)
                  + (v2.x + v2.y + v2.z + v2.w) + (v3.x + v3.y + v3.z + v3.w);
        sum += __shfl_xor_sync(0xffffffffu, sum, 1, 4);
        sum += __shfl_xor_sync(0xffffffffu, sum, 2, 4);

        *(float4*)&sc[r][seg]      = v0;
        *(float4*)&sc[r][seg + 4]  = v1;
        *(float4*)&sc[r][seg + 8]  = v2;
        *(float4*)&sc[r][seg + 12] = v3;
        if ((t & 3) == 0) s_inv[r] = 1.f / sum;
    }
    __syncthreads();

    // ---- out: thread handles rows r0, r0+1, d-quad dq*4 ----
    {
        const int p  = t >> 3;          // 0..31 row pair
        const int dq = t & 7;           // 0..7  d quad
        const int r0 = p * 2;
        float4 o0 = { 0.f, 0.f, 0.f, 0.f };
        float4 o1 = { 0.f, 0.f, 0.f, 0.f };
#pragma unroll
        for (int mc = 0; mc < 16; mc++) {
            float4 p0 = *(const float4*)&sc[r0][mc * 4];
            float4 p1 = *(const float4*)&sc[r0 + 1][mc * 4];
            float4 vv0 = *(const float4*)&vs[mc * 4 + 0][dq * 4];
            float4 vv1 = *(const float4*)&vs[mc * 4 + 1][dq * 4];
            float4 vv2 = *(const float4*)&vs[mc * 4 + 2][dq * 4];
            float4 vv3 = *(const float4*)&vs[mc * 4 + 3][dq * 4];
            o0.x += p0.x*vv0.x + p0.y*vv1.x + p0.z*vv2.x + p0.w*vv3.x;
            o0.y += p0.x*vv0.y + p0.y*vv1.y + p0.z*vv2.y + p0.w*vv3.y;
            o0.z += p0.x*vv0.z + p0.y*vv1.z + p0.z*vv2.z + p0.w*vv3.z;
            o0.w += p0.x*vv0.w + p0.y*vv1.w + p0.z*vv2.w + p0.w*vv3.w;
            o1.x += p1.x*vv0.x + p1.y*vv1.x + p1.z*vv2.x + p1.w*vv3.x;
            o1.y += p1.x*vv0.y + p1.y*vv1.y + p1.z*vv2.y + p1.w*vv3.y;
            o1.z += p1.x*vv0.z + p1.y*vv1.z + p1.z*vv2.z + p1.w*vv3.z;
            o1.w += p1.x*vv0.w + p1.y*vv1.w + p1.z*vv2.w + p1.w*vv3.w;
        }
        const float i0 = s_inv[r0];
        const float i1 = s_inv[r0 + 1];
        o0.x *= i0; o0.y *= i0; o0.z *= i0; o0.w *= i0;
        o1.x *= i1; o1.y *= i1; o1.z *= i1; o1.w *= i1;
        float* op0 = out + (size_t)(b * NTOK + r0) * CDIM + h * HD + dq * 4;
        *(float4*)op0            = o0;
        *(float4*)(op0 + CDIM)   = o1;
    }
}

// ---------------------------------------------------------------------------
// Launch
// ---------------------------------------------------------------------------
extern "C" void kernel_launch(void* const* d_in, const int* in_sizes, int n_in,
                              void* d_out, int out_size)
{
    const float* x       = (const float*)d_in[0];
    const float* qkv_w   = (const float*)d_in[1];
    const float* qkv_b   = (const float*)d_in[2];
    const float* proj_w  = (const float*)d_in[3];
    const float* proj_b  = (const float*)d_in[4];
    const float* table   = (const float*)d_in[5];
    const int*   rpi     = (const int*)  d_in[6];
    float*       out     = (float*)d_out;

    float *qkv_s, *att_s, *bias_s;
    cudaGetSymbolAddress((void**)&qkv_s,  g_qkv);
    cudaGetSymbolAddress((void**)&att_s,  g_att);
    cudaGetSymbolAddress((void**)&bias_s, g_bias);

    cudaFuncSetAttribute(gemm_mma_kernel,
                         cudaFuncAttributeMaxDynamicSharedMemorySize, SMEM_DYN);

    // 0) Precompute per-head bias matrices (tiny)
    bias_kernel<<<dim3(16, NH), 256>>>(table, rpi, bias_s);

    // 1) QKV projection [524288, 768] (tf32 tensor cores)
    gemm_mma_kernel<<<dim3(QKV_N / BN, MROWS / BM), 256, SMEM_DYN>>>(
        x, qkv_w, qkv_b, qkv_s, QKV_N);

    // 2) Window attention
    attn_kernel<<<dim3(B_NW, NH), 256>>>(qkv_s, bias_s, att_s);

    // 3) Output projection [524288, 256] (tf32 tensor cores)
    gemm_mma_kernel<<<dim3(CDIM / BN, MROWS / BM), 256, SMEM_DYN>>>(
        att_s, proj_w, proj_b, out, CDIM);
}

// round 6
// speedup vs baseline: 3.7865x; 1.0849x over previous
#include <cuda_runtime.h>
#include <cstdint>
#include <cstddef>

// ---------------------------------------------------------------------------
// Problem constants
// ---------------------------------------------------------------------------
#define B_NW   8192
#define NTOK   64
#define CDIM   256
#define NH     8
#define HD     32
#define MROWS  (B_NW * NTOK)          // 524288
#define QKV_N  768
#define SCALE  0.17677669529663687f   // 32^-0.5

// GEMM tiling (mma.sync m16n8k8 tf32)
#define BM   128
#define BN   128
#define BK   32
#define NCHUNK (CDIM / BK)            // 8
#define PITCH (BK + 4)                // 36 floats
#define ASZ  (BM * PITCH)
#define BSZ  (BN * PITCH)
#define SMEM_DYN (2 * (ASZ + BSZ) * 4)  // 73728 B

// ---------------------------------------------------------------------------
// Static device scratch
// ---------------------------------------------------------------------------
__device__ float g_qkv[(size_t)MROWS * QKV_N];        // QKV output [M, 768]
__device__ float g_att[(size_t)MROWS * CDIM];         // attention output (tf32-rounded)
__device__ float g_xr [(size_t)MROWS * CDIM];         // x rounded to tf32
__device__ float g_wr [QKV_N * CDIM + CDIM * CDIM];   // rounded qkv_w | proj_w
__device__ float g_bias[NH * NTOK * NTOK];            // precomputed rel-pos bias

// ---------------------------------------------------------------------------
// Helpers
// ---------------------------------------------------------------------------
__device__ __forceinline__ uint32_t s2u(const void* p) {
    uint32_t a;
    asm("{ .reg .u64 t; cvta.to.shared.u64 t, %1; cvt.u32.u64 %0, t; }"
        : "=r"(a) : "l"(p));
    return a;
}

__device__ __forceinline__ float rtf(float x) {   // fp32 -> tf32 (RN), as float
    float y;
    asm("cvt.rna.tf32.f32 %0, %1;" : "=f"(y) : "f"(x));
    return y;
}

__device__ __forceinline__ void cp16(uint32_t dst, const void* src) {
    asm volatile("cp.async.cg.shared.global [%0], [%1], 16;"
                 :: "r"(dst), "l"(src) : "memory");
}

__device__ __forceinline__ void mma8(float* c, const uint32_t* a, const uint32_t* b) {
    asm volatile(
        "mma.sync.aligned.m16n8k8.row.col.f32.tf32.tf32.f32 "
        "{%0,%1,%2,%3}, {%4,%5,%6,%7}, {%8,%9}, {%0,%1,%2,%3};"
        : "+f"(c[0]), "+f"(c[1]), "+f"(c[2]), "+f"(c[3])
        : "r"(a[0]), "r"(a[1]), "r"(a[2]), "r"(a[3]), "r"(b[0]), "r"(b[1]));
}

__device__ __forceinline__ void ldsm4(uint32_t* r, uint32_t addr) {
    asm volatile("ldmatrix.sync.aligned.m8n8.x4.shared.b16 {%0,%1,%2,%3}, [%4];"
                 : "=r"(r[0]), "=r"(r[1]), "=r"(r[2]), "=r"(r[3]) : "r"(addr));
}

// f32x2 packed FMA helpers
__device__ __forceinline__ unsigned long long pack2(float a) {
    unsigned long long r;
    asm("mov.b64 %0, {%1, %1};" : "=l"(r) : "f"(a));
    return r;
}
__device__ __forceinline__ void ffma2(unsigned long long& acc,
                                      unsigned long long a,
                                      unsigned long long b) {
    asm("fma.rn.f32x2 %0, %1, %2, %0;" : "+l"(acc) : "l"(a), "l"(b));
}
__device__ __forceinline__ float2 unpack2(unsigned long long v) {
    float2 r;
    asm("mov.b64 {%0, %1}, %2;" : "=f"(r.x), "=f"(r.y) : "l"(v));
    return r;
}

// Fast exp on the FMA pipe (no MUFU). Valid post max-subtraction (x <= 0).
__device__ __forceinline__ float fexp(float x) {
    float t = fmaxf(x * 1.4426950408889634f, -126.0f);
    float j = rintf(t);
    float f = t - j;
    float p =               1.33335581e-3f;
    p = __fmaf_rn(p, f, 9.61812911e-3f);
    p = __fmaf_rn(p, f, 5.55041087e-2f);
    p = __fmaf_rn(p, f, 2.40226507e-1f);
    p = __fmaf_rn(p, f, 6.93147181e-1f);
    p = __fmaf_rn(p, f, 1.0f);
    int ji = (int)j;
    return p * __int_as_float((ji + 127) << 23);
}

// ---------------------------------------------------------------------------
// tf32 rounding pass (elementwise, float4)
// ---------------------------------------------------------------------------
__global__ __launch_bounds__(256)
void round_tf32_kernel(const float4* __restrict__ s, float4* __restrict__ d, int n4) {
    int i = blockIdx.x * 256 + threadIdx.x;
    if (i < n4) {
        float4 v = s[i];
        v.x = rtf(v.x); v.y = rtf(v.y); v.z = rtf(v.z); v.w = rtf(v.w);
        d[i] = v;
    }
}

// ---------------------------------------------------------------------------
// Precompute bias matrix per head
// ---------------------------------------------------------------------------
__global__ __launch_bounds__(256)
void bias_kernel(const float* __restrict__ table, const int* __restrict__ rpi,
                 float* __restrict__ gb) {
    int h = blockIdx.y;
    int i = blockIdx.x * 256 + threadIdx.x;
    gb[h * 4096 + i] = table[rpi[i] * NH + h];
}

// ---------------------------------------------------------------------------
// tf32 mma.sync GEMM (NT): C = A @ W^T + bias.  A, W pre-rounded to tf32.
// Mainloop: cp.async staging + ldmatrix fragment loads + HMMA only.
// ---------------------------------------------------------------------------
__global__ __launch_bounds__(256, 2)
void gemm_mma_kernel(const float* __restrict__ A,
                     const float* __restrict__ W,
                     const float* __restrict__ bias,
                     float* __restrict__ C,
                     int Ncols)
{
    extern __shared__ float sm[];
    float* As[2] = { sm,       sm + ASZ + BSZ };
    float* Bs[2] = { sm + ASZ, sm + 2 * ASZ + BSZ };

    const int t      = threadIdx.x;
    const int w      = t >> 5;
    const int lane   = t & 31;
    const int g      = lane >> 2;
    const int tg     = lane & 3;
    const int warp_m = w >> 2;
    const int warp_n = w & 3;
    const size_t row0 = (size_t)blockIdx.y * BM;
    const int    col0 = blockIdx.x * BN;

    // ldmatrix per-lane address components
    const int lrow8 = lane & 7;
    const int lsel  = (lane >> 3) & 1;   // 0/1
    const int lhalf = lane >> 4;         // 0/1
    // A x4: matrices = [rows 0-7, k0-3][rows 8-15, k0-3][rows 0-7, k4-7][rows 8-15, k4-7]
    const uint32_t aoff = (uint32_t)((warp_m * 64 + lsel * 8 + lrow8) * PITCH + lhalf * 4) * 4;
    // B x4: matrices = [n 0-7, k0-3][n 0-7, k4-7][n 8-15, k0-3][n 8-15, k4-7]
    const uint32_t boff = (uint32_t)((warp_n * 32 + lhalf * 8 + lrow8) * PITCH + lsel * 4) * 4;

    auto load_chunk = [&](int kc, int buf) {
        const uint32_t aB = s2u(As[buf]);
        const uint32_t bB = s2u(Bs[buf]);
#pragma unroll
        for (int i = 0; i < 4; i++) {
            int u = t + 256 * i;
            int r = u >> 3, q = u & 7;
            cp16(aB + (uint32_t)(r * PITCH + q * 4) * 4,
                 A + (row0 + r) * CDIM + kc * BK + q * 4);
        }
#pragma unroll
        for (int i = 0; i < 4; i++) {
            int u = t + 256 * i;
            int r = u >> 3, q = u & 7;
            cp16(bB + (uint32_t)(r * PITCH + q * 4) * 4,
                 W + (size_t)(col0 + r) * CDIM + kc * BK + q * 4);
        }
        asm volatile("cp.async.commit_group;" ::: "memory");
    };

    float acc[4][4][4];
#pragma unroll
    for (int mi = 0; mi < 4; mi++)
#pragma unroll
        for (int ni = 0; ni < 4; ni++)
#pragma unroll
            for (int j = 0; j < 4; j++) acc[mi][ni][j] = 0.f;

    load_chunk(0, 0);

#pragma unroll
    for (int c = 0; c < NCHUNK; c++) {
        if (c + 1 < NCHUNK) {
            load_chunk(c + 1, (c + 1) & 1);
            asm volatile("cp.async.wait_group 1;" ::: "memory");
        } else {
            asm volatile("cp.async.wait_group 0;" ::: "memory");
        }
        __syncthreads();

        const uint32_t aB = s2u(As[c & 1]) + aoff;
        const uint32_t bB = s2u(Bs[c & 1]) + boff;

#pragma unroll
        for (int ks = 0; ks < 4; ks++) {
            const uint32_t kb = (uint32_t)(ks * 8) * 4;
            uint32_t af[4][4], bf[4][2];
#pragma unroll
            for (int mi = 0; mi < 4; mi++)
                ldsm4(af[mi], aB + (uint32_t)(mi * 16 * PITCH) * 4 + kb);
            {
                uint32_t r[4];
                ldsm4(r, bB + kb);
                bf[0][0] = r[0]; bf[0][1] = r[1]; bf[1][0] = r[2]; bf[1][1] = r[3];
                ldsm4(r, bB + (uint32_t)(16 * PITCH) * 4 + kb);
                bf[2][0] = r[0]; bf[2][1] = r[1]; bf[3][0] = r[2]; bf[3][1] = r[3];
            }
#pragma unroll
            for (int mi = 0; mi < 4; mi++)
#pragma unroll
                for (int ni = 0; ni < 4; ni++)
                    mma8(acc[mi][ni], af[mi], bf[ni]);
        }
        __syncthreads();
    }

#pragma unroll
    for (int ni = 0; ni < 4; ni++) {
        const int col = col0 + warp_n * 32 + ni * 8 + 2 * tg;
        const float bx = __ldg(&bias[col]);
        const float by = __ldg(&bias[col + 1]);
#pragma unroll
        for (int mi = 0; mi < 4; mi++) {
            const size_t rlo = row0 + warp_m * 64 + mi * 16 + g;
            float2 v0 = { acc[mi][ni][0] + bx, acc[mi][ni][1] + by };
            float2 v1 = { acc[mi][ni][2] + bx, acc[mi][ni][3] + by };
            *(float2*)(C + rlo * (size_t)Ncols + col)       = v0;
            *(float2*)(C + (rlo + 8) * (size_t)Ncols + col) = v1;
        }
    }
}

// ---------------------------------------------------------------------------
// Window attention: one block per (window b, head h). 256 threads.
// f32x2 packed FMA in score/out phases; output rounded to tf32.
// ---------------------------------------------------------------------------
__global__ __launch_bounds__(256)
void attn_kernel(const float* __restrict__ qkv,
                 const float* __restrict__ gbias,
                 float* __restrict__ out)
{
    __shared__ float qs[NTOK][36];    // q (pre-scaled)
    __shared__ float kT[HD][68];      // transposed k
    __shared__ float vs[NTOK][36];
    __shared__ float sc[NTOK][68];
    __shared__ float s_inv[NTOK];

    const int b = blockIdx.x;
    const int h = blockIdx.y;
    const int t = threadIdx.x;

    const float* base  = qkv + (size_t)b * NTOK * QKV_N;
    const float* biash = gbias + h * NTOK * NTOK;

    for (int i = t; i < 3 * 512; i += 256) {
        int which = i >> 9;
        int rem   = i & 511;
        int r     = rem >> 3;
        int f     = rem & 7;
        float4 v4 = *(const float4*)(base + (size_t)r * QKV_N + which * CDIM + h * HD + f * 4);
        if (which == 0) {
            v4.x *= SCALE; v4.y *= SCALE; v4.z *= SCALE; v4.w *= SCALE;
            *(float4*)&qs[r][f * 4] = v4;
        } else if (which == 1) {
            kT[f * 4 + 0][r] = v4.x;
            kT[f * 4 + 1][r] = v4.y;
            kT[f * 4 + 2][r] = v4.z;
            kT[f * 4 + 3][r] = v4.w;
        } else {
            *(float4*)&vs[r][f * 4] = v4;
        }
    }
    __syncthreads();

    // ---- scores: 16x16 thread grid, 4 rows x 4 cols per thread, f32x2 ----
    {
        const int ti = t >> 4;
        const int tj = t & 15;
        const int r0 = ti * 4;
        const int m0 = tj * 4;
        unsigned long long accp[4][2];
#pragma unroll
        for (int i = 0; i < 4; i++) { accp[i][0] = 0ULL; accp[i][1] = 0ULL; }

#pragma unroll
        for (int dc = 0; dc < 8; dc++) {
            float4 qv[4];
            ulonglong2 kvp[4];
#pragma unroll
            for (int i = 0; i < 4; i++) qv[i] = *(const float4*)&qs[r0 + i][dc * 4];
#pragma unroll
            for (int s = 0; s < 4; s++)
                kvp[s] = *(const ulonglong2*)&kT[dc * 4 + s][m0];
#pragma unroll
            for (int i = 0; i < 4; i++) {
                unsigned long long q0 = pack2(qv[i].x);
                unsigned long long q1 = pack2(qv[i].y);
                unsigned long long q2 = pack2(qv[i].z);
                unsigned long long q3 = pack2(qv[i].w);
                ffma2(accp[i][0], q0, kvp[0].x); ffma2(accp[i][1], q0, kvp[0].y);
                ffma2(accp[i][0], q1, kvp[1].x); ffma2(accp[i][1], q1, kvp[1].y);
                ffma2(accp[i][0], q2, kvp[2].x); ffma2(accp[i][1], q2, kvp[2].y);
                ffma2(accp[i][0], q3, kvp[3].x); ffma2(accp[i][1], q3, kvp[3].y);
            }
        }
#pragma unroll
        for (int i = 0; i < 4; i++) {
            float2 a0 = unpack2(accp[i][0]);
            float2 a1 = unpack2(accp[i][1]);
            float4 bv = *(const float4*)(biash + (r0 + i) * NTOK + m0);
            float4 o = { a0.x + bv.x, a0.y + bv.y, a1.x + bv.z, a1.y + bv.w };
            *(float4*)&sc[r0 + i][m0] = o;
        }
    }
    __syncthreads();

    // ---- softmax: 4 threads per row ----
    {
        const int r   = t >> 2;
        const int seg = (t & 3) * 16;
        float4 v0 = *(const float4*)&sc[r][seg];
        float4 v1 = *(const float4*)&sc[r][seg + 4];
        float4 v2 = *(const float4*)&sc[r][seg + 8];
        float4 v3 = *(const float4*)&sc[r][seg + 12];
        float mx = fmaxf(fmaxf(fmaxf(v0.x, v0.y), fmaxf(v0.z, v0.w)),
                   fmaxf(fmaxf(fmaxf(v1.x, v1.y), fmaxf(v1.z, v1.w)),
                   fmaxf(fmaxf(fmaxf(v2.x, v2.y), fmaxf(v2.z, v2.w)),
                         fmaxf(fmaxf(v3.x, v3.y), fmaxf(v3.z, v3.w)))));
        mx = fmaxf(mx, __shfl_xor_sync(0xffffffffu, mx, 1, 4));
        mx = fmaxf(mx, __shfl_xor_sync(0xffffffffu, mx, 2, 4));

        v0.x = fexp(v0.x - mx); v0.y = fexp(v0.y - mx);
        v0.z = fexp(v0.z - mx); v0.w = fexp(v0.w - mx);
        v1.x = fexp(v1.x - mx); v1.y = fexp(v1.y - mx);
        v1.z = fexp(v1.z - mx); v1.w = fexp(v1.w - mx);
        v2.x = fexp(v2.x - mx); v2.y = fexp(v2.y - mx);
        v2.z = fexp(v2.z - mx); v2.w = fexp(v2.w - mx);
        v3.x = fexp(v3.x - mx); v3.y = fexp(v3.y - mx);
        v3.z = fexp(v3.z - mx); v3.w = fexp(v3.w - mx);

        float sum = (v0.x + v0.y + v0.z + v0.w) + (v1.x + v1.y + v1.z + v1.w)
                  + (v2.x + v2.y + v2.z + v2.w) + (v3.x + v3.y + v3.z + v3.w);
        sum += __shfl_xor_sync(0xffffffffu, sum, 1, 4);
        sum += __shfl_xor_sync(0xffffffffu, sum, 2, 4);

        *(float4*)&sc[r][seg]      = v0;
        *(float4*)&sc[r][seg + 4]  = v1;
        *(float4*)&sc[r][seg + 8]  = v2;
        *(float4*)&sc[r][seg + 12] = v3;
        if ((t & 3) == 0) s_inv[r] = 1.f / sum;
    }
    __syncthreads();

    // ---- out: 2 rows x 4 d per thread, f32x2; rounded to tf32 ----
    {
        const int p  = t >> 3;
        const int dq = t & 7;
        const int r0 = p * 2;
        unsigned long long o0[2] = { 0ULL, 0ULL };
        unsigned long long o1[2] = { 0ULL, 0ULL };
#pragma unroll
        for (int mc = 0; mc < 16; mc++) {
            float4 p0 = *(const float4*)&sc[r0][mc * 4];
            float4 p1 = *(const float4*)&sc[r0 + 1][mc * 4];
            ulonglong2 vv[4];
#pragma unroll
            for (int s = 0; s < 4; s++)
                vv[s] = *(const ulonglong2*)&vs[mc * 4 + s][dq * 4];
            {
                unsigned long long a;
                a = pack2(p0.x); ffma2(o0[0], a, vv[0].x); ffma2(o0[1], a, vv[0].y);
                a = pack2(p0.y); ffma2(o0[0], a, vv[1].x); ffma2(o0[1], a, vv[1].y);
                a = pack2(p0.z); ffma2(o0[0], a, vv[2].x); ffma2(o0[1], a, vv[2].y);
                a = pack2(p0.w); ffma2(o0[0], a, vv[3].x); ffma2(o0[1], a, vv[3].y);
                a = pack2(p1.x); ffma2(o1[0], a, vv[0].x); ffma2(o1[1], a, vv[0].y);
                a = pack2(p1.y); ffma2(o1[0], a, vv[1].x); ffma2(o1[1], a, vv[1].y);
                a = pack2(p1.z); ffma2(o1[0], a, vv[2].x); ffma2(o1[1], a, vv[2].y);
                a = pack2(p1.w); ffma2(o1[0], a, vv[3].x); ffma2(o1[1], a, vv[3].y);
            }
        }
        const float i0 = s_inv[r0];
        const float i1 = s_inv[r0 + 1];
        float2 a0 = unpack2(o0[0]), a1 = unpack2(o0[1]);
        float2 b0 = unpack2(o1[0]), b1 = unpack2(o1[1]);
        float4 w0 = { rtf(a0.x * i0), rtf(a0.y * i0), rtf(a1.x * i0), rtf(a1.y * i0) };
        float4 w1 = { rtf(b0.x * i1), rtf(b0.y * i1), rtf(b1.x * i1), rtf(b1.y * i1) };
        float* op0 = out + (size_t)(b * NTOK + r0) * CDIM + h * HD + dq * 4;
        *(float4*)op0          = w0;
        *(float4*)(op0 + CDIM) = w1;
    }
}

// ---------------------------------------------------------------------------
// Launch
// ---------------------------------------------------------------------------
extern "C" void kernel_launch(void* const* d_in, const int* in_sizes, int n_in,
                              void* d_out, int out_size)
{
    const float* x       = (const float*)d_in[0];
    const float* qkv_w   = (const float*)d_in[1];
    const float* qkv_b   = (const float*)d_in[2];
    const float* proj_w  = (const float*)d_in[3];
    const float* proj_b  = (const float*)d_in[4];
    const float* table   = (const float*)d_in[5];
    const int*   rpi     = (const int*)  d_in[6];
    float*       out     = (float*)d_out;

    float *qkv_s, *att_s, *xr_s, *wr_s, *bias_s;
    cudaGetSymbolAddress((void**)&qkv_s,  g_qkv);
    cudaGetSymbolAddress((void**)&att_s,  g_att);
    cudaGetSymbolAddress((void**)&xr_s,   g_xr);
    cudaGetSymbolAddress((void**)&wr_s,   g_wr);
    cudaGetSymbolAddress((void**)&bias_s, g_bias);
    float* wqkv_r  = wr_s;
    float* wproj_r = wr_s + QKV_N * CDIM;

    cudaFuncSetAttribute(gemm_mma_kernel,
                         cudaFuncAttributeMaxDynamicSharedMemorySize, SMEM_DYN);

    // 0) Precompute bias matrices + RN-round MMA inputs to tf32
    bias_kernel<<<dim3(16, NH), 256>>>(table, rpi, bias_s);
    {
        int n4x = MROWS * CDIM / 4;
        round_tf32_kernel<<<n4x / 256, 256>>>((const float4*)x, (float4*)xr_s, n4x);
        int n4w1 = QKV_N * CDIM / 4;
        round_tf32_kernel<<<(n4w1 + 255) / 256, 256>>>((const float4*)qkv_w, (float4*)wqkv_r, n4w1);
        int n4w2 = CDIM * CDIM / 4;
        round_tf32_kernel<<<(n4w2 + 255) / 256, 256>>>((const float4*)proj_w, (float4*)wproj_r, n4w2);
    }

    // 1) QKV projection (tf32 tensor cores, pre-rounded inputs)
    gemm_mma_kernel<<<dim3(QKV_N / BN, MROWS / BM), 256, SMEM_DYN>>>(
        xr_s, wqkv_r, qkv_b, qkv_s, QKV_N);

    // 2) Window attention (rounds its output to tf32)
    attn_kernel<<<dim3(B_NW, NH), 256>>>(qkv_s, bias_s, att_s);

    // 3) Output projection (tf32 tensor cores)
    gemm_mma_kernel<<<dim3(CDIM / BN, MROWS / BM), 256, SMEM_DYN>>>(
        att_s, wproj_r, proj_b, out, CDIM);
}

// round 7
// speedup vs baseline: 3.8029x; 1.0043x over previous
#include <cuda_runtime.h>
#include <cstdint>
#include <cstddef>

// ---------------------------------------------------------------------------
// Problem constants
// ---------------------------------------------------------------------------
#define B_NW   8192
#define NTOK   64
#define CDIM   256
#define NH     8
#define HD     32
#define MROWS  (B_NW * NTOK)          // 524288
#define QKV_N  768
#define SCALE  0.17677669529663687f   // 32^-0.5

// GEMM tiling (mma.sync m16n8k8 tf32)
#define BM   128
#define BN   128
#define BK   32
#define NCHUNK (CDIM / BK)            // 8
#define PITCH (BK + 4)                // 36 floats
#define ASZ  (BM * PITCH)
#define BSZ  (BN * PITCH)
#define SMEM_DYN (2 * (ASZ + BSZ) * 4)  // 73728 B

// ---------------------------------------------------------------------------
// Static device scratch
// ---------------------------------------------------------------------------
__device__ float g_qkv[(size_t)MROWS * QKV_N];        // QKV output [M, 768]
__device__ float g_att[(size_t)MROWS * CDIM];         // attention out (tf32-rounded)
__device__ float g_wr [QKV_N * CDIM + CDIM * CDIM];   // rounded qkv_w | proj_w
__device__ float g_bias[NH * NTOK * NTOK];            // precomputed rel-pos bias

// ---------------------------------------------------------------------------
// Helpers
// ---------------------------------------------------------------------------
__device__ __forceinline__ uint32_t s2u(const void* p) {
    uint32_t a;
    asm("{ .reg .u64 t; cvta.to.shared.u64 t, %1; cvt.u32.u64 %0, t; }"
        : "=r"(a) : "l"(p));
    return a;
}

__device__ __forceinline__ float rtf(float x) {   // fp32 -> tf32 (RN), as float
    float y;
    asm("cvt.rna.tf32.f32 %0, %1;" : "=f"(y) : "f"(x));
    return y;
}

__device__ __forceinline__ void rtf_r(uint32_t& u) {  // in-place on b32 reg
    asm("cvt.rna.tf32.f32 %0, %0;" : "+r"(u));
}

__device__ __forceinline__ void cp16(uint32_t dst, const void* src) {
    asm volatile("cp.async.cg.shared.global [%0], [%1], 16;"
                 :: "r"(dst), "l"(src) : "memory");
}

__device__ __forceinline__ void mma8(float* c, const uint32_t* a, const uint32_t* b) {
    asm volatile(
        "mma.sync.aligned.m16n8k8.row.col.f32.tf32.tf32.f32 "
        "{%0,%1,%2,%3}, {%4,%5,%6,%7}, {%8,%9}, {%0,%1,%2,%3};"
        : "+f"(c[0]), "+f"(c[1]), "+f"(c[2]), "+f"(c[3])
        : "r"(a[0]), "r"(a[1]), "r"(a[2]), "r"(a[3]), "r"(b[0]), "r"(b[1]));
}

__device__ __forceinline__ void ldsm4(uint32_t* r, uint32_t addr) {
    asm volatile("ldmatrix.sync.aligned.m8n8.x4.shared.b16 {%0,%1,%2,%3}, [%4];"
                 : "=r"(r[0]), "=r"(r[1]), "=r"(r[2]), "=r"(r[3]) : "r"(addr));
}

// f32x2 packed FMA helpers
__device__ __forceinline__ unsigned long long pack2(float a) {
    unsigned long long r;
    asm("mov.b64 %0, {%1, %1};" : "=l"(r) : "f"(a));
    return r;
}
__device__ __forceinline__ void ffma2(unsigned long long& acc,
                                      unsigned long long a,
                                      unsigned long long b) {
    asm("fma.rn.f32x2 %0, %1, %2, %0;" : "+l"(acc) : "l"(a), "l"(b));
}
__device__ __forceinline__ float2 unpack2(unsigned long long v) {
    float2 r;
    asm("mov.b64 {%0, %1}, %2;" : "=f"(r.x), "=f"(r.y) : "l"(v));
    return r;
}

// Fast exp on the FMA pipe (no MUFU). Valid post max-subtraction (x <= 0).
__device__ __forceinline__ float fexp(float x) {
    float t = fmaxf(x * 1.4426950408889634f, -126.0f);
    float j = rintf(t);
    float f = t - j;
    float p =               1.33335581e-3f;
    p = __fmaf_rn(p, f, 9.61812911e-3f);
    p = __fmaf_rn(p, f, 5.55041087e-2f);
    p = __fmaf_rn(p, f, 2.40226507e-1f);
    p = __fmaf_rn(p, f, 6.93147181e-1f);
    p = __fmaf_rn(p, f, 1.0f);
    int ji = (int)j;
    return p * __int_as_float((ji + 127) << 23);
}

// ---------------------------------------------------------------------------
// tf32 rounding pass (weights only now — tiny)
// ---------------------------------------------------------------------------
__global__ __launch_bounds__(256)
void round_tf32_kernel(const float4* __restrict__ s, float4* __restrict__ d, int n4) {
    int i = blockIdx.x * 256 + threadIdx.x;
    if (i < n4) {
        float4 v = s[i];
        v.x = rtf(v.x); v.y = rtf(v.y); v.z = rtf(v.z); v.w = rtf(v.w);
        d[i] = v;
    }
}

// ---------------------------------------------------------------------------
// Precompute bias matrix per head
// ---------------------------------------------------------------------------
__global__ __launch_bounds__(256)
void bias_kernel(const float* __restrict__ table, const int* __restrict__ rpi,
                 float* __restrict__ gb) {
    int h = blockIdx.y;
    int i = blockIdx.x * 256 + threadIdx.x;
    gb[h * 4096 + i] = table[rpi[i] * NH + h];
}

// ---------------------------------------------------------------------------
// tf32 mma.sync GEMM (NT): C = A @ W^T + bias.
// CVT_A: round A fragments to tf32 in-register (A may be raw fp32).
// W must be pre-rounded. Mainloop: cp.async + ldmatrix + HMMA.
// ---------------------------------------------------------------------------
template<bool CVT_A>
__global__ __launch_bounds__(256, 2)
void gemm_mma_kernel(const float* __restrict__ A,
                     const float* __restrict__ W,
                     const float* __restrict__ bias,
                     float* __restrict__ C,
                     int Ncols)
{
    extern __shared__ float sm[];
    float* As[2] = { sm,       sm + ASZ + BSZ };
    float* Bs[2] = { sm + ASZ, sm + 2 * ASZ + BSZ };

    const int t      = threadIdx.x;
    const int w      = t >> 5;
    const int lane   = t & 31;
    const int g      = lane >> 2;
    const int tg     = lane & 3;
    const int warp_m = w >> 2;
    const int warp_n = w & 3;
    const size_t row0 = (size_t)blockIdx.y * BM;
    const int    col0 = blockIdx.x * BN;

    const int lrow8 = lane & 7;
    const int lsel  = (lane >> 3) & 1;
    const int lhalf = lane >> 4;
    const uint32_t aoff = (uint32_t)((warp_m * 64 + lsel * 8 + lrow8) * PITCH + lhalf * 4) * 4;
    const uint32_t boff = (uint32_t)((warp_n * 32 + lhalf * 8 + lrow8) * PITCH + lsel * 4) * 4;

    auto load_chunk = [&](int kc, int buf) {
        const uint32_t aB = s2u(As[buf]);
        const uint32_t bB = s2u(Bs[buf]);
#pragma unroll
        for (int i = 0; i < 4; i++) {
            int u = t + 256 * i;
            int r = u >> 3, q = u & 7;
            cp16(aB + (uint32_t)(r * PITCH + q * 4) * 4,
                 A + (row0 + r) * CDIM + kc * BK + q * 4);
        }
#pragma unroll
        for (int i = 0; i < 4; i++) {
            int u = t + 256 * i;
            int r = u >> 3, q = u & 7;
            cp16(bB + (uint32_t)(r * PITCH + q * 4) * 4,
                 W + (size_t)(col0 + r) * CDIM + kc * BK + q * 4);
        }
        asm volatile("cp.async.commit_group;" ::: "memory");
    };

    float acc[4][4][4];
#pragma unroll
    for (int mi = 0; mi < 4; mi++)
#pragma unroll
        for (int ni = 0; ni < 4; ni++)
#pragma unroll
            for (int j = 0; j < 4; j++) acc[mi][ni][j] = 0.f;

    load_chunk(0, 0);

#pragma unroll
    for (int c = 0; c < NCHUNK; c++) {
        if (c + 1 < NCHUNK) {
            load_chunk(c + 1, (c + 1) & 1);
            asm volatile("cp.async.wait_group 1;" ::: "memory");
        } else {
            asm volatile("cp.async.wait_group 0;" ::: "memory");
        }
        __syncthreads();

        const uint32_t aB = s2u(As[c & 1]) + aoff;
        const uint32_t bB = s2u(Bs[c & 1]) + boff;

#pragma unroll
        for (int ks = 0; ks < 4; ks++) {
            const uint32_t kb = (uint32_t)(ks * 8) * 4;
            uint32_t af[4][4], bf[4][2];
#pragma unroll
            for (int mi = 0; mi < 4; mi++) {
                ldsm4(af[mi], aB + (uint32_t)(mi * 16 * PITCH) * 4 + kb);
                if (CVT_A) {
                    rtf_r(af[mi][0]); rtf_r(af[mi][1]);
                    rtf_r(af[mi][2]); rtf_r(af[mi][3]);
                }
            }
            {
                uint32_t r[4];
                ldsm4(r, bB + kb);
                bf[0][0] = r[0]; bf[0][1] = r[1]; bf[1][0] = r[2]; bf[1][1] = r[3];
                ldsm4(r, bB + (uint32_t)(16 * PITCH) * 4 + kb);
                bf[2][0] = r[0]; bf[2][1] = r[1]; bf[3][0] = r[2]; bf[3][1] = r[3];
            }
#pragma unroll
            for (int mi = 0; mi < 4; mi++)
#pragma unroll
                for (int ni = 0; ni < 4; ni++)
                    mma8(acc[mi][ni], af[mi], bf[ni]);
        }
        __syncthreads();
    }

#pragma unroll
    for (int ni = 0; ni < 4; ni++) {
        const int col = col0 + warp_n * 32 + ni * 8 + 2 * tg;
        const float bx = __ldg(&bias[col]);
        const float by = __ldg(&bias[col + 1]);
#pragma unroll
        for (int mi = 0; mi < 4; mi++) {
            const size_t rlo = row0 + warp_m * 64 + mi * 16 + g;
            float2 v0 = { acc[mi][ni][0] + bx, acc[mi][ni][1] + by };
            float2 v1 = { acc[mi][ni][2] + bx, acc[mi][ni][3] + by };
            *(float2*)(C + rlo * (size_t)Ncols + col)       = v0;
            *(float2*)(C + (rlo + 8) * (size_t)Ncols + col) = v1;
        }
    }
}

// ---------------------------------------------------------------------------
// Window attention: one block per (window b, head h). 256 threads.
// f32x2 packed FMA; output rounded to tf32 (feeds gemm2 cvt-free).
// ---------------------------------------------------------------------------
__global__ __launch_bounds__(256)
void attn_kernel(const float* __restrict__ qkv,
                 const float* __restrict__ gbias,
                 float* __restrict__ out)
{
    __shared__ float qs[NTOK][36];
    __shared__ float kT[HD][68];
    __shared__ float vs[NTOK][36];
    __shared__ float sc[NTOK][68];
    __shared__ float s_inv[NTOK];

    const int b = blockIdx.x;
    const int h = blockIdx.y;
    const int t = threadIdx.x;

    const float* base  = qkv + (size_t)b * NTOK * QKV_N;
    const float* biash = gbias + h * NTOK * NTOK;

    for (int i = t; i < 3 * 512; i += 256) {
        int which = i >> 9;
        int rem   = i & 511;
        int r     = rem >> 3;
        int f     = rem & 7;
        float4 v4 = *(const float4*)(base + (size_t)r * QKV_N + which * CDIM + h * HD + f * 4);
        if (which == 0) {
            v4.x *= SCALE; v4.y *= SCALE; v4.z *= SCALE; v4.w *= SCALE;
            *(float4*)&qs[r][f * 4] = v4;
        } else if (which == 1) {
            kT[f * 4 + 0][r] = v4.x;
            kT[f * 4 + 1][r] = v4.y;
            kT[f * 4 + 2][r] = v4.z;
            kT[f * 4 + 3][r] = v4.w;
        } else {
            *(float4*)&vs[r][f * 4] = v4;
        }
    }
    __syncthreads();

    // ---- scores ----
    {
        const int ti = t >> 4;
        const int tj = t & 15;
        const int r0 = ti * 4;
        const int m0 = tj * 4;
        unsigned long long accp[4][2];
#pragma unroll
        for (int i = 0; i < 4; i++) { accp[i][0] = 0ULL; accp[i][1] = 0ULL; }

#pragma unroll
        for (int dc = 0; dc < 8; dc++) {
            float4 qv[4];
            ulonglong2 kvp[4];
#pragma unroll
            for (int i = 0; i < 4; i++) qv[i] = *(const float4*)&qs[r0 + i][dc * 4];
#pragma unroll
            for (int s = 0; s < 4; s++)
                kvp[s] = *(const ulonglong2*)&kT[dc * 4 + s][m0];
#pragma unroll
            for (int i = 0; i < 4; i++) {
                unsigned long long q0 = pack2(qv[i].x);
                unsigned long long q1 = pack2(qv[i].y);
                unsigned long long q2 = pack2(qv[i].z);
                unsigned long long q3 = pack2(qv[i].w);
                ffma2(accp[i][0], q0, kvp[0].x); ffma2(accp[i][1], q0, kvp[0].y);
                ffma2(accp[i][0], q1, kvp[1].x); ffma2(accp[i][1], q1, kvp[1].y);
                ffma2(accp[i][0], q2, kvp[2].x); ffma2(accp[i][1], q2, kvp[2].y);
                ffma2(accp[i][0], q3, kvp[3].x); ffma2(accp[i][1], q3, kvp[3].y);
            }
        }
#pragma unroll
        for (int i = 0; i < 4; i++) {
            float2 a0 = unpack2(accp[i][0]);
            float2 a1 = unpack2(accp[i][1]);
            float4 bv = *(const float4*)(biash + (r0 + i) * NTOK + m0);
            float4 o = { a0.x + bv.x, a0.y + bv.y, a1.x + bv.z, a1.y + bv.w };
            *(float4*)&sc[r0 + i][m0] = o;
        }
    }
    __syncthreads();

    // ---- softmax: 4 threads per row ----
    {
        const int r   = t >> 2;
        const int seg = (t & 3) * 16;
        float4 v0 = *(const float4*)&sc[r][seg];
        float4 v1 = *(const float4*)&sc[r][seg + 4];
        float4 v2 = *(const float4*)&sc[r][seg + 8];
        float4 v3 = *(const float4*)&sc[r][seg + 12];
        float mx = fmaxf(fmaxf(fmaxf(v0.x, v0.y), fmaxf(v0.z, v0.w)),
                   fmaxf(fmaxf(fmaxf(v1.x, v1.y), fmaxf(v1.z, v1.w)),
                   fmaxf(fmaxf(fmaxf(v2.x, v2.y), fmaxf(v2.z, v2.w)),
                         fmaxf(fmaxf(v3.x, v3.y), fmaxf(v3.z, v3.w)))));
        mx = fmaxf(mx, __shfl_xor_sync(0xffffffffu, mx, 1, 4));
        mx = fmaxf(mx, __shfl_xor_sync(0xffffffffu, mx, 2, 4));

        v0.x = fexp(v0.x - mx); v0.y = fexp(v0.y - mx);
        v0.z = fexp(v0.z - mx); v0.w = fexp(v0.w - mx);
        v1.x = fexp(v1.x - mx); v1.y = fexp(v1.y - mx);
        v1.z = fexp(v1.z - mx); v1.w = fexp(v1.w - mx);
        v2.x = fexp(v2.x - mx); v2.y = fexp(v2.y - mx);
        v2.z = fexp(v2.z - mx); v2.w = fexp(v2.w - mx);
        v3.x = fexp(v3.x - mx); v3.y = fexp(v3.y - mx);
        v3.z = fexp(v3.z - mx); v3.w = fexp(v3.w - mx);

        float sum = (v0.x + v0.y + v0.z + v0.w) + (v1.x + v1.y + v1.z + v1.w)
                  + (v2.x + v2.y + v2.z + v2.w) + (v3.x + v3.y + v3.z + v3.w);
        sum += __shfl_xor_sync(0xffffffffu, sum, 1, 4);
        sum += __shfl_xor_sync(0xffffffffu, sum, 2, 4);

        *(float4*)&sc[r][seg]      = v0;
        *(float4*)&sc[r][seg + 4]  = v1;
        *(float4*)&sc[r][seg + 8]  = v2;
        *(float4*)&sc[r][seg + 12] = v3;
        if ((t & 3) == 0) s_inv[r] = 1.f / sum;
    }
    __syncthreads();

    // ---- out: 2 rows x 4 d per thread, f32x2; rounded to tf32 ----
    {
        const int p  = t >> 3;
        const int dq = t & 7;
        const int r0 = p * 2;
        unsigned long long o0[2] = { 0ULL, 0ULL };
        unsigned long long o1[2] = { 0ULL, 0ULL };
#pragma unroll
        for (int mc = 0; mc < 16; mc++) {
            float4 p0 = *(const float4*)&sc[r0][mc * 4];
            float4 p1 = *(const float4*)&sc[r0 + 1][mc * 4];
            ulonglong2 vv[4];
#pragma unroll
            for (int s = 0; s < 4; s++)
                vv[s] = *(const ulonglong2*)&vs[mc * 4 + s][dq * 4];
            {
                unsigned long long a;
                a = pack2(p0.x); ffma2(o0[0], a, vv[0].x); ffma2(o0[1], a, vv[0].y);
                a = pack2(p0.y); ffma2(o0[0], a, vv[1].x); ffma2(o0[1], a, vv[1].y);
                a = pack2(p0.z); ffma2(o0[0], a, vv[2].x); ffma2(o0[1], a, vv[2].y);
                a = pack2(p0.w); ffma2(o0[0], a, vv[3].x); ffma2(o0[1], a, vv[3].y);
                a = pack2(p1.x); ffma2(o1[0], a, vv[0].x); ffma2(o1[1], a, vv[0].y);
                a = pack2(p1.y); ffma2(o1[0], a, vv[1].x); ffma2(o1[1], a, vv[1].y);
                a = pack2(p1.z); ffma2(o1[0], a, vv[2].x); ffma2(o1[1], a, vv[2].y);
                a = pack2(p1.w); ffma2(o1[0], a, vv[3].x); ffma2(o1[1], a, vv[3].y);
            }
        }
        const float i0 = s_inv[r0];
        const float i1 = s_inv[r0 + 1];
        float2 a0 = unpack2(o0[0]), a1 = unpack2(o0[1]);
        float2 b0 = unpack2(o1[0]), b1 = unpack2(o1[1]);
        float4 w0 = { rtf(a0.x * i0), rtf(a0.y * i0), rtf(a1.x * i0), rtf(a1.y * i0) };
        float4 w1 = { rtf(b0.x * i1), rtf(b0.y * i1), rtf(b1.x * i1), rtf(b1.y * i1) };
        float* op0 = out + (size_t)(b * NTOK + r0) * CDIM + h * HD + dq * 4;
        *(float4*)op0          = w0;
        *(float4*)(op0 + CDIM) = w1;
    }
}

// ---------------------------------------------------------------------------
// Launch
// ---------------------------------------------------------------------------
extern "C" void kernel_launch(void* const* d_in, const int* in_sizes, int n_in,
                              void* d_out, int out_size)
{
    const float* x       = (const float*)d_in[0];
    const float* qkv_w   = (const float*)d_in[1];
    const float* qkv_b   = (const float*)d_in[2];
    const float* proj_w  = (const float*)d_in[3];
    const float* proj_b  = (const float*)d_in[4];
    const float* table   = (const float*)d_in[5];
    const int*   rpi     = (const int*)  d_in[6];
    float*       out     = (float*)d_out;

    float *qkv_s, *att_s, *wr_s, *bias_s;
    cudaGetSymbolAddress((void**)&qkv_s,  g_qkv);
    cudaGetSymbolAddress((void**)&att_s,  g_att);
    cudaGetSymbolAddress((void**)&wr_s,   g_wr);
    cudaGetSymbolAddress((void**)&bias_s, g_bias);
    float* wqkv_r  = wr_s;
    float* wproj_r = wr_s + QKV_N * CDIM;

    cudaFuncSetAttribute(gemm_mma_kernel<true>,
                         cudaFuncAttributeMaxDynamicSharedMemorySize, SMEM_DYN);
    cudaFuncSetAttribute(gemm_mma_kernel<false>,
                         cudaFuncAttributeMaxDynamicSharedMemorySize, SMEM_DYN);

    // 0) Precompute bias matrices + RN-round weights (tiny)
    bias_kernel<<<dim3(16, NH), 256>>>(table, rpi, bias_s);
    {
        int n4w1 = QKV_N * CDIM / 4;
        round_tf32_kernel<<<(n4w1 + 255) / 256, 256>>>((const float4*)qkv_w, (float4*)wqkv_r, n4w1);
        int n4w2 = CDIM * CDIM / 4;
        round_tf32_kernel<<<(n4w2 + 255) / 256, 256>>>((const float4*)proj_w, (float4*)wproj_r, n4w2);
    }

    // 1) QKV projection: A = raw x, rounded in-register (CVT_A=true)
    gemm_mma_kernel<true><<<dim3(QKV_N / BN, MROWS / BM), 256, SMEM_DYN>>>(
        x, wqkv_r, qkv_b, qkv_s, QKV_N);

    // 2) Window attention (rounds its output to tf32)
    attn_kernel<<<dim3(B_NW, NH), 256>>>(qkv_s, bias_s, att_s);

    // 3) Output projection: A pre-rounded by attention (CVT_A=false)
    gemm_mma_kernel<false><<<dim3(CDIM / BN, MROWS / BM), 256, SMEM_DYN>>>(
        att_s, wproj_r, proj_b, out, CDIM);
}

// round 8
// speedup vs baseline: 3.8918x; 1.0234x over previous
#include <cuda_runtime.h>
#include <cstdint>
#include <cstddef>

// ---------------------------------------------------------------------------
// Problem constants
// ---------------------------------------------------------------------------
#define B_NW   8192
#define NTOK   64
#define CDIM   256
#define NH     8
#define HD     32
#define MROWS  (B_NW * NTOK)          // 524288
#define QKV_N  768
#define SCALE  0.17677669529663687f   // 32^-0.5

// GEMM tiling (mma.sync m16n8k8 tf32)
#define BM   128
#define BN   128
#define BK   32
#define NCHUNK (CDIM / BK)            // 8
#define STAGES 3
#define PITCH (BK + 4)                // 36 floats
#define ASZ  (BM * PITCH)
#define BSZ  (BN * PITCH)
#define STG_FLOATS (ASZ + BSZ)
#define SMEM_DYN (STAGES * STG_FLOATS * 4)   // 110592 B

// ---------------------------------------------------------------------------
// Static device scratch
// ---------------------------------------------------------------------------
__device__ float g_qkv[(size_t)MROWS * QKV_N];        // QKV output [M, 768]
__device__ float g_att[(size_t)MROWS * CDIM];         // attention out (tf32-rounded)
__device__ float g_wr [QKV_N * CDIM + CDIM * CDIM];   // rounded qkv_w | proj_w
__device__ float g_bias[NH * NTOK * NTOK];            // precomputed rel-pos bias

// ---------------------------------------------------------------------------
// Helpers
// ---------------------------------------------------------------------------
__device__ __forceinline__ uint32_t s2u(const void* p) {
    uint32_t a;
    asm("{ .reg .u64 t; cvta.to.shared.u64 t, %1; cvt.u32.u64 %0, t; }"
        : "=r"(a) : "l"(p));
    return a;
}

__device__ __forceinline__ float rtf(float x) {
    float y;
    asm("cvt.rna.tf32.f32 %0, %1;" : "=f"(y) : "f"(x));
    return y;
}

__device__ __forceinline__ void rtf_r(uint32_t& u) {
    asm("cvt.rna.tf32.f32 %0, %0;" : "+r"(u));
}

__device__ __forceinline__ void cp16(uint32_t dst, const void* src) {
    asm volatile("cp.async.cg.shared.global [%0], [%1], 16;"
                 :: "r"(dst), "l"(src) : "memory");
}

__device__ __forceinline__ void mma8(float* c, const uint32_t* a, const uint32_t* b) {
    asm volatile(
        "mma.sync.aligned.m16n8k8.row.col.f32.tf32.tf32.f32 "
        "{%0,%1,%2,%3}, {%4,%5,%6,%7}, {%8,%9}, {%0,%1,%2,%3};"
        : "+f"(c[0]), "+f"(c[1]), "+f"(c[2]), "+f"(c[3])
        : "r"(a[0]), "r"(a[1]), "r"(a[2]), "r"(a[3]), "r"(b[0]), "r"(b[1]));
}

__device__ __forceinline__ void ldsm4(uint32_t* r, uint32_t addr) {
    asm volatile("ldmatrix.sync.aligned.m8n8.x4.shared.b16 {%0,%1,%2,%3}, [%4];"
                 : "=r"(r[0]), "=r"(r[1]), "=r"(r[2]), "=r"(r[3]) : "r"(addr));
}

// f32x2 packed FMA helpers
__device__ __forceinline__ unsigned long long pack2(float a) {
    unsigned long long r;
    asm("mov.b64 %0, {%1, %1};" : "=l"(r) : "f"(a));
    return r;
}
__device__ __forceinline__ void ffma2(unsigned long long& acc,
                                      unsigned long long a,
                                      unsigned long long b) {
    asm("fma.rn.f32x2 %0, %1, %2, %0;" : "+l"(acc) : "l"(a), "l"(b));
}
__device__ __forceinline__ float2 unpack2(unsigned long long v) {
    float2 r;
    asm("mov.b64 {%0, %1}, %2;" : "=f"(r.x), "=f"(r.y) : "l"(v));
    return r;
}

// Fast exp on the FMA pipe (no MUFU). Valid post max-subtraction (x <= 0).
__device__ __forceinline__ float fexp(float x) {
    float t = fmaxf(x * 1.4426950408889634f, -126.0f);
    float j = rintf(t);
    float f = t - j;
    float p =               1.33335581e-3f;
    p = __fmaf_rn(p, f, 9.61812911e-3f);
    p = __fmaf_rn(p, f, 5.55041087e-2f);
    p = __fmaf_rn(p, f, 2.40226507e-1f);
    p = __fmaf_rn(p, f, 6.93147181e-1f);
    p = __fmaf_rn(p, f, 1.0f);
    int ji = (int)j;
    return p * __int_as_float((ji + 127) << 23);
}

// ---------------------------------------------------------------------------
// tf32 rounding pass (weights only — tiny)
// ---------------------------------------------------------------------------
__global__ __launch_bounds__(256)
void round_tf32_kernel(const float4* __restrict__ s, float4* __restrict__ d, int n4) {
    int i = blockIdx.x * 256 + threadIdx.x;
    if (i < n4) {
        float4 v = s[i];
        v.x = rtf(v.x); v.y = rtf(v.y); v.z = rtf(v.z); v.w = rtf(v.w);
        d[i] = v;
    }
}

// ---------------------------------------------------------------------------
// Precompute bias matrix per head
// ---------------------------------------------------------------------------
__global__ __launch_bounds__(256)
void bias_kernel(const float* __restrict__ table, const int* __restrict__ rpi,
                 float* __restrict__ gb) {
    int h = blockIdx.y;
    int i = blockIdx.x * 256 + threadIdx.x;
    gb[h * 4096 + i] = table[rpi[i] * NH + h];
}

// ---------------------------------------------------------------------------
// tf32 mma.sync GEMM (NT): C = A @ W^T + bias.
// 3-stage cp.async pipeline, ONE __syncthreads per K-chunk.
// CVT_A: round A fragments to tf32 in-register. W pre-rounded.
// ---------------------------------------------------------------------------
template<bool CVT_A>
__global__ __launch_bounds__(256, 2)
void gemm_mma_kernel(const float* __restrict__ A,
                     const float* __restrict__ W,
                     const float* __restrict__ bias,
                     float* __restrict__ C,
                     int Ncols)
{
    extern __shared__ float sm[];

    const int t      = threadIdx.x;
    const int w      = t >> 5;
    const int lane   = t & 31;
    const int g      = lane >> 2;
    const int tg     = lane & 3;
    const int warp_m = w >> 2;
    const int warp_n = w & 3;
    const size_t row0 = (size_t)blockIdx.y * BM;
    const int    col0 = blockIdx.x * BN;

    const int lrow8 = lane & 7;
    const int lsel  = (lane >> 3) & 1;
    const int lhalf = lane >> 4;
    const uint32_t aoff = (uint32_t)((warp_m * 64 + lsel * 8 + lrow8) * PITCH + lhalf * 4) * 4;
    const uint32_t boff = (uint32_t)((warp_n * 32 + lhalf * 8 + lrow8) * PITCH + lsel * 4) * 4;

    const uint32_t smb = s2u(sm);

    auto load_chunk = [&](int kc, int stg) {
        const uint32_t aB = smb + (uint32_t)(stg * STG_FLOATS) * 4;
        const uint32_t bB = aB + (uint32_t)ASZ * 4;
#pragma unroll
        for (int i = 0; i < 4; i++) {
            int u = t + 256 * i;
            int r = u >> 3, q = u & 7;
            cp16(aB + (uint32_t)(r * PITCH + q * 4) * 4,
                 A + (row0 + r) * CDIM + kc * BK + q * 4);
        }
#pragma unroll
        for (int i = 0; i < 4; i++) {
            int u = t + 256 * i;
            int r = u >> 3, q = u & 7;
            cp16(bB + (uint32_t)(r * PITCH + q * 4) * 4,
                 W + (size_t)(col0 + r) * CDIM + kc * BK + q * 4);
        }
        asm volatile("cp.async.commit_group;" ::: "memory");
    };

    float acc[4][4][4];
#pragma unroll
    for (int mi = 0; mi < 4; mi++)
#pragma unroll
        for (int ni = 0; ni < 4; ni++)
#pragma unroll
            for (int j = 0; j < 4; j++) acc[mi][ni][j] = 0.f;

    // prologue: 2 chunks in flight
    load_chunk(0, 0);
    load_chunk(1, 1);

#pragma unroll
    for (int c = 0; c < NCHUNK; c++) {
        const int stg = c % STAGES;
        // ensure chunk c is resident
        if (c < NCHUNK - 1) asm volatile("cp.async.wait_group 1;" ::: "memory");
        else                asm volatile("cp.async.wait_group 0;" ::: "memory");
        __syncthreads();
        // buffer (c+2)%STAGES == (c-1)%STAGES is free now: all warps passed the
        // barrier after consuming chunk c-1. Issue next load immediately.
        if (c + 2 < NCHUNK) load_chunk(c + 2, (c + 2) % STAGES);

        const uint32_t aB = smb + (uint32_t)(stg * STG_FLOATS) * 4 + aoff;
        const uint32_t bB = smb + (uint32_t)(stg * STG_FLOATS + ASZ) * 4 + boff;

#pragma unroll
        for (int ks = 0; ks < 4; ks++) {
            const uint32_t kb = (uint32_t)(ks * 8) * 4;
            uint32_t af[4][4], bf[4][2];
#pragma unroll
            for (int mi = 0; mi < 4; mi++) {
                ldsm4(af[mi], aB + (uint32_t)(mi * 16 * PITCH) * 4 + kb);
                if (CVT_A) {
                    rtf_r(af[mi][0]); rtf_r(af[mi][1]);
                    rtf_r(af[mi][2]); rtf_r(af[mi][3]);
                }
            }
            {
                uint32_t r[4];
                ldsm4(r, bB + kb);
                bf[0][0] = r[0]; bf[0][1] = r[1]; bf[1][0] = r[2]; bf[1][1] = r[3];
                ldsm4(r, bB + (uint32_t)(16 * PITCH) * 4 + kb);
                bf[2][0] = r[0]; bf[2][1] = r[1]; bf[3][0] = r[2]; bf[3][1] = r[3];
            }
#pragma unroll
            for (int mi = 0; mi < 4; mi++)
#pragma unroll
                for (int ni = 0; ni < 4; ni++)
                    mma8(acc[mi][ni], af[mi], bf[ni]);
        }
    }

#pragma unroll
    for (int ni = 0; ni < 4; ni++) {
        const int col = col0 + warp_n * 32 + ni * 8 + 2 * tg;
        const float bx = __ldg(&bias[col]);
        const float by = __ldg(&bias[col + 1]);
#pragma unroll
        for (int mi = 0; mi < 4; mi++) {
            const size_t rlo = row0 + warp_m * 64 + mi * 16 + g;
            float2 v0 = { acc[mi][ni][0] + bx, acc[mi][ni][1] + by };
            float2 v1 = { acc[mi][ni][2] + bx, acc[mi][ni][3] + by };
            *(float2*)(C + rlo * (size_t)Ncols + col)       = v0;
            *(float2*)(C + (rlo + 8) * (size_t)Ncols + col) = v1;
        }
    }
}

// ---------------------------------------------------------------------------
// Window attention: one block per (window b, head h). 256 threads.
// f32x2 packed FMA; output rounded to tf32 (feeds gemm2 cvt-free).
// ---------------------------------------------------------------------------
__global__ __launch_bounds__(256)
void attn_kernel(const float* __restrict__ qkv,
                 const float* __restrict__ gbias,
                 float* __restrict__ out)
{
    __shared__ float qs[NTOK][36];
    __shared__ float kT[HD][68];
    __shared__ float vs[NTOK][36];
    __shared__ float sc[NTOK][68];
    __shared__ float s_inv[NTOK];

    const int b = blockIdx.x;
    const int h = blockIdx.y;
    const int t = threadIdx.x;

    const float* base  = qkv + (size_t)b * NTOK * QKV_N;
    const float* biash = gbias + h * NTOK * NTOK;

    for (int i = t; i < 3 * 512; i += 256) {
        int which = i >> 9;
        int rem   = i & 511;
        int r     = rem >> 3;
        int f     = rem & 7;
        float4 v4 = *(const float4*)(base + (size_t)r * QKV_N + which * CDIM + h * HD + f * 4);
        if (which == 0) {
            v4.x *= SCALE; v4.y *= SCALE; v4.z *= SCALE; v4.w *= SCALE;
            *(float4*)&qs[r][f * 4] = v4;
        } else if (which == 1) {
            kT[f * 4 + 0][r] = v4.x;
            kT[f * 4 + 1][r] = v4.y;
            kT[f * 4 + 2][r] = v4.z;
            kT[f * 4 + 3][r] = v4.w;
        } else {
            *(float4*)&vs[r][f * 4] = v4;
        }
    }
    __syncthreads();

    // ---- scores ----
    {
        const int ti = t >> 4;
        const int tj = t & 15;
        const int r0 = ti * 4;
        const int m0 = tj * 4;
        unsigned long long accp[4][2];
#pragma unroll
        for (int i = 0; i < 4; i++) { accp[i][0] = 0ULL; accp[i][1] = 0ULL; }

#pragma unroll
        for (int dc = 0; dc < 8; dc++) {
            float4 qv[4];
            ulonglong2 kvp[4];
#pragma unroll
            for (int i = 0; i < 4; i++) qv[i] = *(const float4*)&qs[r0 + i][dc * 4];
#pragma unroll
            for (int s = 0; s < 4; s++)
                kvp[s] = *(const ulonglong2*)&kT[dc * 4 + s][m0];
#pragma unroll
            for (int i = 0; i < 4; i++) {
                unsigned long long q0 = pack2(qv[i].x);
                unsigned long long q1 = pack2(qv[i].y);
                unsigned long long q2 = pack2(qv[i].z);
                unsigned long long q3 = pack2(qv[i].w);
                ffma2(accp[i][0], q0, kvp[0].x); ffma2(accp[i][1], q0, kvp[0].y);
                ffma2(accp[i][0], q1, kvp[1].x); ffma2(accp[i][1], q1, kvp[1].y);
                ffma2(accp[i][0], q2, kvp[2].x); ffma2(accp[i][1], q2, kvp[2].y);
                ffma2(accp[i][0], q3, kvp[3].x); ffma2(accp[i][1], q3, kvp[3].y);
            }
        }
#pragma unroll
        for (int i = 0; i < 4; i++) {
            float2 a0 = unpack2(accp[i][0]);
            float2 a1 = unpack2(accp[i][1]);
            float4 bv = *(const float4*)(biash + (r0 + i) * NTOK + m0);
            float4 o = { a0.x + bv.x, a0.y + bv.y, a1.x + bv.z, a1.y + bv.w };
            *(float4*)&sc[r0 + i][m0] = o;
        }
    }
    __syncthreads();

    // ---- softmax: 4 threads per row ----
    {
        const int r   = t >> 2;
        const int seg = (t & 3) * 16;
        float4 v0 = *(const float4*)&sc[r][seg];
        float4 v1 = *(const float4*)&sc[r][seg + 4];
        float4 v2 = *(const float4*)&sc[r][seg + 8];
        float4 v3 = *(const float4*)&sc[r][seg + 12];
        float mx = fmaxf(fmaxf(fmaxf(v0.x, v0.y), fmaxf(v0.z, v0.w)),
                   fmaxf(fmaxf(fmaxf(v1.x, v1.y), fmaxf(v1.z, v1.w)),
                   fmaxf(fmaxf(fmaxf(v2.x, v2.y), fmaxf(v2.z, v2.w)),
                         fmaxf(fmaxf(v3.x, v3.y), fmaxf(v3.z, v3.w)))));
        mx = fmaxf(mx, __shfl_xor_sync(0xffffffffu, mx, 1, 4));
        mx = fmaxf(mx, __shfl_xor_sync(0xffffffffu, mx, 2, 4));

        v0.x = fexp(v0.x - mx); v0.y = fexp(v0.y - mx);
        v0.z = fexp(v0.z - mx); v0.w = fexp(v0.w - mx);
        v1.x = fexp(v1.x - mx); v1.y = fexp(v1.y - mx);
        v1.z = fexp(v1.z - mx); v1.w = fexp(v1.w - mx);
        v2.x = fexp(v2.x - mx); v2.y = fexp(v2.y - mx);
        v2.z = fexp(v2.z - mx); v2.w = fexp(v2.w - mx);
        v3.x = fexp(v3.x - mx); v3.y = fexp(v3.y - mx);
        v3.z = fexp(v3.z - mx); v3.w = fexp(v3.w - mx);

        float sum = (v0.x + v0.y + v0.z + v0.w) + (v1.x + v1.y + v1.z + v1.w)
                  + (v2.x + v2.y + v2.z + v2.w) + (v3.x + v3.y + v3.z + v3.w);
        sum += __shfl_xor_sync(0xffffffffu, sum, 1, 4);
        sum += __shfl_xor_sync(0xffffffffu, sum, 2, 4);

        *(float4*)&sc[r][seg]      = v0;
        *(float4*)&sc[r][seg + 4]  = v1;
        *(float4*)&sc[r][seg + 8]  = v2;
        *(float4*)&sc[r][seg + 12] = v3;
        if ((t & 3) == 0) s_inv[r] = 1.f / sum;
    }
    __syncthreads();

    // ---- out: 2 rows x 4 d per thread, f32x2; rounded to tf32 ----
    {
        const int p  = t >> 3;
        const int dq = t & 7;
        const int r0 = p * 2;
        unsigned long long o0[2] = { 0ULL, 0ULL };
        unsigned long long o1[2] = { 0ULL, 0ULL };
#pragma unroll
        for (int mc = 0; mc < 16; mc++) {
            float4 p0 = *(const float4*)&sc[r0][mc * 4];
            float4 p1 = *(const float4*)&sc[r0 + 1][mc * 4];
            ulonglong2 vv[4];
#pragma unroll
            for (int s = 0; s < 4; s++)
                vv[s] = *(const ulonglong2*)&vs[mc * 4 + s][dq * 4];
            {
                unsigned long long a;
                a = pack2(p0.x); ffma2(o0[0], a, vv[0].x); ffma2(o0[1], a, vv[0].y);
                a = pack2(p0.y); ffma2(o0[0], a, vv[1].x); ffma2(o0[1], a, vv[1].y);
                a = pack2(p0.z); ffma2(o0[0], a, vv[2].x); ffma2(o0[1], a, vv[2].y);
                a = pack2(p0.w); ffma2(o0[0], a, vv[3].x); ffma2(o0[1], a, vv[3].y);
                a = pack2(p1.x); ffma2(o1[0], a, vv[0].x); ffma2(o1[1], a, vv[0].y);
                a = pack2(p1.y); ffma2(o1[0], a, vv[1].x); ffma2(o1[1], a, vv[1].y);
                a = pack2(p1.z); ffma2(o1[0], a, vv[2].x); ffma2(o1[1], a, vv[2].y);
                a = pack2(p1.w); ffma2(o1[0], a, vv[3].x); ffma2(o1[1], a, vv[3].y);
            }
        }
        const float i0 = s_inv[r0];
        const float i1 = s_inv[r0 + 1];
        float2 a0 = unpack2(o0[0]), a1 = unpack2(o0[1]);
        float2 b0 = unpack2(o1[0]), b1 = unpack2(o1[1]);
        float4 w0 = { rtf(a0.x * i0), rtf(a0.y * i0), rtf(a1.x * i0), rtf(a1.y * i0) };
        float4 w1 = { rtf(b0.x * i1), rtf(b0.y * i1), rtf(b1.x * i1), rtf(b1.y * i1) };
        float* op0 = out + (size_t)(b * NTOK + r0) * CDIM + h * HD + dq * 4;
        *(float4*)op0          = w0;
        *(float4*)(op0 + CDIM) = w1;
    }
}

// ---------------------------------------------------------------------------
// Launch
// ---------------------------------------------------------------------------
extern "C" void kernel_launch(void* const* d_in, const int* in_sizes, int n_in,
                              void* d_out, int out_size)
{
    const float* x       = (const float*)d_in[0];
    const float* qkv_w   = (const float*)d_in[1];
    const float* qkv_b   = (const float*)d_in[2];
    const float* proj_w  = (const float*)d_in[3];
    const float* proj_b  = (const float*)d_in[4];
    const float* table   = (const float*)d_in[5];
    const int*   rpi     = (const int*)  d_in[6];
    float*       out     = (float*)d_out;

    float *qkv_s, *att_s, *wr_s, *bias_s;
    cudaGetSymbolAddress((void**)&qkv_s,  g_qkv);
    cudaGetSymbolAddress((void**)&att_s,  g_att);
    cudaGetSymbolAddress((void**)&wr_s,   g_wr);
    cudaGetSymbolAddress((void**)&bias_s, g_bias);
    float* wqkv_r  = wr_s;
    float* wproj_r = wr_s + QKV_N * CDIM;

    cudaFuncSetAttribute(gemm_mma_kernel<true>,
                         cudaFuncAttributeMaxDynamicSharedMemorySize, SMEM_DYN);
    cudaFuncSetAttribute(gemm_mma_kernel<false>,
                         cudaFuncAttributeMaxDynamicSharedMemorySize, SMEM_DYN);

    // 0) Precompute bias matrices + RN-round weights (tiny)
    bias_kernel<<<dim3(16, NH), 256>>>(table, rpi, bias_s);
    {
        int n4w1 = QKV_N * CDIM / 4;
        round_tf32_kernel<<<(n4w1 + 255) / 256, 256>>>((const float4*)qkv_w, (float4*)wqkv_r, n4w1);
        int n4w2 = CDIM * CDIM / 4;
        round_tf32_kernel<<<(n4w2 + 255) / 256, 256>>>((const float4*)proj_w, (float4*)wproj_r, n4w2);
    }

    // 1) QKV projection: A = raw x, rounded in-register (CVT_A=true)
    gemm_mma_kernel<true><<<dim3(QKV_N / BN, MROWS / BM), 256, SMEM_DYN>>>(
        x, wqkv_r, qkv_b, qkv_s, QKV_N);

    // 2) Window attention (rounds its output to tf32)
    attn_kernel<<<dim3(B_NW, NH), 256>>>(qkv_s, bias_s, att_s);

    // 3) Output projection: A pre-rounded by attention (CVT_A=false)
    gemm_mma_kernel<false><<<dim3(CDIM / BN, MROWS / BM), 256, SMEM_DYN>>>(
        att_s, wproj_r, proj_b, out, CDIM);
}